// round 9
// baseline (speedup 1.0000x reference)
#include <cuda_runtime.h>
#include <cuda_bf16.h>
#include <cstdint>

// Problem constants (fixed by the dataset)
#define NUM_NODES 20000
#define NUM_EDGES 65536
#define WIDTH     64
#define EDGE_FEAT 6
#define HIDDEN    128
#define PLANES    129            // 128 W2 planes + 1 bias(b2) plane -> g_xb

// Scratch (allocation-free rule: __device__ globals)
__device__ float g_h [(size_t)NUM_EDGES * HIDDEN];                 // 33.5 MB
__device__ float g_g [(size_t)NUM_NODES * HIDDEN * WIDTH];         // 655 MB  g[n][k][v]
__device__ float g_xb[(size_t)NUM_NODES * WIDTH];                  // 5.1 MB
__device__ __nv_bfloat16 g_wt_hi[(size_t)PLANES * WIDTH * WIDTH];  // Wt[k][v][w] hi
__device__ __nv_bfloat16 g_wt_lo[(size_t)PLANES * WIDTH * WIDTH];  // Wt[k][v][w] lo
// edge sort-by-sender
__device__ int g_cnt[NUM_NODES];
__device__ int g_off[NUM_NODES + 1];
__device__ int g_perm[NUM_EDGES];

__device__ __forceinline__ void split_bf16(float a, unsigned short& hi, unsigned short& lo) {
    __nv_bfloat16 h = __float2bfloat16_rn(a);
    float r = a - __bfloat162float(h);
    __nv_bfloat16 l = __float2bfloat16_rn(r);
    hi = __bfloat16_as_ushort(h);
    lo = __bfloat16_as_ushort(l);
}

// Warp-level bf16 MMA (sm_80 PTX feature set — valid for plain sm_103 target)
#define MMA_BF16(c, a, b0, b1) \
    asm volatile("mma.sync.aligned.m16n8k16.row.col.f32.bf16.bf16.f32 " \
        "{%0,%1,%2,%3}, {%4,%5,%6,%7}, {%8,%9}, {%0,%1,%2,%3};" \
        : "+f"((c)[0]), "+f"((c)[1]), "+f"((c)[2]), "+f"((c)[3]) \
        : "r"((a)[0]), "r"((a)[1]), "r"((a)[2]), "r"((a)[3]), "r"(b0), "r"(b1))

#define CP_ASYNC16(dst_u32, src) \
    asm volatile("cp.async.cg.shared.global [%0], [%1], 16;" :: "r"(dst_u32), "l"(src))
#define CP_COMMIT() asm volatile("cp.async.commit_group;")
#define CP_WAIT1()  asm volatile("cp.async.wait_group 1;")
#define CP_WAIT0()  asm volatile("cp.async.wait_group 0;")

__device__ __forceinline__ uint32_t smem_u32(const void* p) {
    uint32_t a;
    asm("{ .reg .u64 t; cvta.to.shared.u64 t, %1; cvt.u32.u64 %0, t; }" : "=r"(a) : "l"(p));
    return a;
}

// ---------------------------------------------------------------------------
// Zero kernels
// ---------------------------------------------------------------------------
__global__ void k_zero(float* __restrict__ out, int n) {
    int i = blockIdx.x * blockDim.x + threadIdx.x;
    if (i < n) out[i] = 0.f;
}
__global__ void k_zero_cnt() {
    int i = blockIdx.x * blockDim.x + threadIdx.x;
    if (i < NUM_NODES) g_cnt[i] = 0;
}

// ---------------------------------------------------------------------------
// h[e][k] = relu( sum_f edge_attr[e][f] * W1[f][k] + b1[k] )
// ---------------------------------------------------------------------------
__global__ void k_hidden(const float* __restrict__ ea,
                         const float* __restrict__ W1,
                         const float* __restrict__ b1) {
    int idx = blockIdx.x * blockDim.x + threadIdx.x;
    if (idx >= NUM_EDGES * HIDDEN) return;
    int e = idx >> 7;
    int j = idx & (HIDDEN - 1);
    const float* a = ea + (size_t)e * EDGE_FEAT;
    float s = __ldg(b1 + j);
    #pragma unroll
    for (int f = 0; f < EDGE_FEAT; f++)
        s = fmaf(__ldg(a + f), __ldg(W1 + f * HIDDEN + j), s);
    g_h[idx] = fmaxf(s, 0.f);
}

// ---------------------------------------------------------------------------
// Wt[k][v][w] = W2[k][w*64+v] (k<128) or b2[w*64+v] (k==128), split bf16 hi/lo
// ---------------------------------------------------------------------------
__global__ void k_prep_w2(const float* __restrict__ W2, const float* __restrict__ b2) {
    int idx = blockIdx.x * blockDim.x + threadIdx.x;
    if (idx >= PLANES * WIDTH * WIDTH) return;
    int k = idx >> 12, rem = idx & 4095, v = rem >> 6, w = rem & 63;
    float val = (k < HIDDEN) ? W2[(size_t)k * 4096 + w * 64 + v] : b2[w * 64 + v];
    unsigned short hi, lo;
    split_bf16(val, hi, lo);
    g_wt_hi[idx] = __ushort_as_bfloat16(hi);
    g_wt_lo[idx] = __ushort_as_bfloat16(lo);
}

// ---------------------------------------------------------------------------
// Edge sort-by-sender: count -> scan (1 block) -> fill perm
// ---------------------------------------------------------------------------
__global__ void k_count(const int* __restrict__ snd) {
    int i = blockIdx.x * blockDim.x + threadIdx.x;
    if (i < NUM_EDGES) atomicAdd(&g_cnt[snd[i]], 1);
}
__global__ __launch_bounds__(1024) void k_scan() {
    __shared__ int ps[1024];
    const int tid = threadIdx.x;
    const int CH  = (NUM_NODES + 1023) / 1024;   // 20
    const int base = tid * CH;
    int s = 0;
    for (int j = 0; j < CH; j++) {
        int i = base + j;
        if (i < NUM_NODES) s += g_cnt[i];
    }
    ps[tid] = s;
    __syncthreads();
    for (int d = 1; d < 1024; d <<= 1) {         // Hillis-Steele inclusive scan
        int v = (tid >= d) ? ps[tid - d] : 0;
        __syncthreads();
        ps[tid] += v;
        __syncthreads();
    }
    int run = ps[tid] - s;                        // exclusive prefix of chunk
    for (int j = 0; j < CH; j++) {
        int i = base + j;
        if (i < NUM_NODES) { g_off[i] = run; run += g_cnt[i]; g_cnt[i] = 0; }
    }
    if (tid == 1023) g_off[NUM_NODES] = run;
}
__global__ void k_fill(const int* __restrict__ snd) {
    int i = blockIdx.x * blockDim.x + threadIdx.x;
    if (i >= NUM_EDGES) return;
    int s = snd[i];
    int pos = g_off[s] + atomicAdd(&g_cnt[s], 1);
    g_perm[pos] = i;
}

// ---------------------------------------------------------------------------
// HMMA g-GEMM: g[n][k][v] = sum_w x[n][w]*Wt[k][v][w]; plane 128 -> g_xb.
// CTA = 128-node M-tile; 8 warps (4m x 2n), 32x32 C tile each.
// Split-bf16 (AhBh + AhBl + AlBh). A in smem (re-read per kt, low regs);
// B double-buffered via cp.async (no prefetch registers, no STS window).
// Smem rows padded to KP=72 bf16 -> provably conflict-free fragment LDS.
// ---------------------------------------------------------------------------
#define KP 72
#define ROWB (KP * 2)                        // 144 bytes per padded row
#define SMA_HI 0
#define SMA_LO (128 * ROWB)                  // 18432
#define SMB_BASE (2 * 128 * ROWB)            // 36864
#define SMB(p, hl) (SMB_BASE + (p) * 18432 + (hl) * 9216)
#define SM_TOT (SMB_BASE + 2 * 18432)        // 73728 bytes

__global__ __launch_bounds__(256) void k_gmat_hmma(const float* __restrict__ x) {
    extern __shared__ char sm[];
    const uint32_t sb = smem_u32(sm);
    const int t    = threadIdx.x;
    const int lane = t & 31;
    const int warp = t >> 5;
    const int wm   = warp & 3;
    const int wn   = warp >> 2;
    const int n0   = blockIdx.x * 128;
    const int g    = lane >> 2;
    const int l4   = lane & 3;

    const uint4* wh4 = (const uint4*)g_wt_hi;
    const uint4* wl4 = (const uint4*)g_wt_lo;

    // async-stage plane k's B (hi+lo, 16KB) into buffer p
    auto stageB = [&](int k, int p) {
        const size_t base = (size_t)k * 512;      // 512 uint4 per plane
        #pragma unroll
        for (int q = 0; q < 2; q++) {
            const int i = t + q * 256;            // chunk: row=i>>3, c=i&7
            const uint32_t off = (uint32_t)(i >> 3) * ROWB + (i & 7) * 16;
            CP_ASYNC16(sb + SMB(p, 0) + off, wh4 + base + i);
            CP_ASYNC16(sb + SMB(p, 1) + off, wl4 + base + i);
        }
    };

    // ---- Stage A tile: x rows -> bf16 hi/lo, padded rows ----
    {
        const int row  = t >> 1;
        const int half = t & 1;
        const int n    = n0 + row;
        float4 f4[8];
        if (n < NUM_NODES) {
            const float4* xr = (const float4*)(x + (size_t)n * WIDTH) + half * 8;
            #pragma unroll
            for (int j = 0; j < 8; j++) f4[j] = xr[j];
        } else {
            #pragma unroll
            for (int j = 0; j < 8; j++) f4[j] = make_float4(0.f, 0.f, 0.f, 0.f);
        }
        const float* f = (const float*)f4;
        #pragma unroll
        for (int c = 0; c < 4; c++) {
            uint32_t hw[4], lw[4];
            #pragma unroll
            for (int j = 0; j < 4; j++) {
                unsigned short h0, l0, h1, l1;
                split_bf16(f[c * 8 + j * 2 + 0], h0, l0);
                split_bf16(f[c * 8 + j * 2 + 1], h1, l1);
                hw[j] = (uint32_t)h0 | ((uint32_t)h1 << 16);
                lw[j] = (uint32_t)l0 | ((uint32_t)l1 << 16);
            }
            const uint32_t off = (uint32_t)row * ROWB + half * 64 + c * 16;
            *(uint4*)(sm + SMA_HI + off) = make_uint4(hw[0], hw[1], hw[2], hw[3]);
            *(uint4*)(sm + SMA_LO + off) = make_uint4(lw[0], lw[1], lw[2], lw[3]);
        }
    }

    stageB(0, 0); CP_COMMIT();
    stageB(1, 1); CP_COMMIT();

    for (int k = 0; k < PLANES; k++) {
        const int p = k & 1;
        if (k + 1 < PLANES) { CP_WAIT1(); } else { CP_WAIT0(); }
        __syncthreads();                      // buf p data + (k==0) A tile visible

        float C[2][4][4];
        #pragma unroll
        for (int mt = 0; mt < 2; mt++)
            #pragma unroll
            for (int nt = 0; nt < 4; nt++)
                #pragma unroll
                for (int i = 0; i < 4; i++) C[mt][nt][i] = 0.f;

        #pragma unroll
        for (int kt = 0; kt < 4; kt++) {
            // A frags for this kt (hi/lo), conflict-free LDS
            uint32_t Ah[2][4], Al[2][4];
            #pragma unroll
            for (int mt = 0; mt < 2; mt++) {
                const int r0 = wm * 32 + mt * 16 + g;
                const int cb = kt * 16 + l4 * 2;
                Ah[mt][0] = *(const uint32_t*)(sm + SMA_HI + (size_t)r0 * ROWB + cb * 2);
                Ah[mt][1] = *(const uint32_t*)(sm + SMA_HI + (size_t)(r0 + 8) * ROWB + cb * 2);
                Ah[mt][2] = *(const uint32_t*)(sm + SMA_HI + (size_t)r0 * ROWB + (cb + 8) * 2);
                Ah[mt][3] = *(const uint32_t*)(sm + SMA_HI + (size_t)(r0 + 8) * ROWB + (cb + 8) * 2);
                Al[mt][0] = *(const uint32_t*)(sm + SMA_LO + (size_t)r0 * ROWB + cb * 2);
                Al[mt][1] = *(const uint32_t*)(sm + SMA_LO + (size_t)(r0 + 8) * ROWB + cb * 2);
                Al[mt][2] = *(const uint32_t*)(sm + SMA_LO + (size_t)r0 * ROWB + (cb + 8) * 2);
                Al[mt][3] = *(const uint32_t*)(sm + SMA_LO + (size_t)(r0 + 8) * ROWB + (cb + 8) * 2);
            }
            #pragma unroll
            for (int nt = 0; nt < 4; nt++) {
                const uint32_t boff =
                    (uint32_t)(wn * 32 + nt * 8 + g) * ROWB + (kt * 16 + l4 * 2) * 2;
                const uint32_t bh0 = *(const uint32_t*)(sm + SMB(p, 0) + boff);
                const uint32_t bh1 = *(const uint32_t*)(sm + SMB(p, 0) + boff + 16);
                const uint32_t bl0 = *(const uint32_t*)(sm + SMB(p, 1) + boff);
                const uint32_t bl1 = *(const uint32_t*)(sm + SMB(p, 1) + boff + 16);
                #pragma unroll
                for (int mt = 0; mt < 2; mt++) {
                    MMA_BF16(C[mt][nt], Ah[mt], bh0, bh1);
                    MMA_BF16(C[mt][nt], Ah[mt], bl0, bl1);
                    MMA_BF16(C[mt][nt], Al[mt], bh0, bh1);
                }
            }
        }

        // Store: planes 0..127 -> g_g[n][k][v]; plane 128 -> g_xb[n][v]
        #pragma unroll
        for (int mt = 0; mt < 2; mt++) {
            const int n1 = n0 + wm * 32 + mt * 16 + g;
            const int n2 = n1 + 8;
            #pragma unroll
            for (int nt = 0; nt < 4; nt++) {
                const int col = wn * 32 + nt * 8 + l4 * 2;
                float* d1 = (k < HIDDEN)
                    ? g_g + ((size_t)n1 * HIDDEN + k) * WIDTH + col
                    : g_xb + (size_t)n1 * WIDTH + col;
                float* d2 = (k < HIDDEN)
                    ? g_g + ((size_t)n2 * HIDDEN + k) * WIDTH + col
                    : g_xb + (size_t)n2 * WIDTH + col;
                if (n1 < NUM_NODES) *(float2*)d1 = make_float2(C[mt][nt][0], C[mt][nt][1]);
                if (n2 < NUM_NODES) *(float2*)d2 = make_float2(C[mt][nt][2], C[mt][nt][3]);
            }
        }

        __syncthreads();                      // all warps done reading buf p
        if (k + 2 < PLANES) { stageB(k + 2, p); CP_COMMIT(); }
    }
}

// ---------------------------------------------------------------------------
// Per edge (sender-sorted via g_perm): msg[v] = sum_k h[e][k]*g[s][k][v] + xb[s][v]
// atomicAdd into out[r][v]. Warp per edge; relu-sparsity skips zero planes;
// sorted order -> same-sender g rows hit L1/L2 instead of DRAM.
// ---------------------------------------------------------------------------
__global__ __launch_bounds__(256) void k_msg(const int* __restrict__ senders,
                                             const int* __restrict__ receivers,
                                             float* __restrict__ out) {
    __shared__ float hs[8][HIDDEN];
    const int wi   = threadIdx.x >> 5;
    const int lane = threadIdx.x & 31;
    const int i    = blockIdx.x * 8 + wi;
    if (i >= NUM_EDGES) return;
    const int e = g_perm[i];

    #pragma unroll
    for (int j = 0; j < HIDDEN / 32; j++)
        hs[wi][j * 32 + lane] = g_h[(size_t)e * HIDDEN + j * 32 + lane];
    __syncwarp();

    const int s = senders[e];
    const int r = receivers[e];

    const float2* gp = (const float2*)(g_g + (size_t)s * HIDDEN * WIDTH) + lane;
    float2 acc = ((const float2*)(g_xb + (size_t)s * WIDTH))[lane];

    #pragma unroll 8
    for (int k = 0; k < HIDDEN; k++) {
        float hk = hs[wi][k];
        if (hk != 0.f) {
            float2 gv = gp[k * 32];
            acc.x = fmaf(hk, gv.x, acc.x);
            acc.y = fmaf(hk, gv.y, acc.y);
        }
    }

    atomicAdd(out + (size_t)r * WIDTH + 2 * lane,     acc.x);
    atomicAdd(out + (size_t)r * WIDTH + 2 * lane + 1, acc.y);
}

// ---------------------------------------------------------------------------
// Launch chain (default stream, sequential deps)
// ---------------------------------------------------------------------------
extern "C" void kernel_launch(void* const* d_in, const int* in_sizes, int n_in,
                              void* d_out, int out_size) {
    const float* x   = (const float*)d_in[0];
    const float* ea  = (const float*)d_in[1];
    const float* W1  = (const float*)d_in[2];
    const float* b1  = (const float*)d_in[3];
    const float* W2  = (const float*)d_in[4];
    const float* b2  = (const float*)d_in[5];
    const int*   snd = (const int*)d_in[6];
    const int*   rcv = (const int*)d_in[7];
    float* out = (float*)d_out;

    cudaFuncSetAttribute(k_gmat_hmma, cudaFuncAttributeMaxDynamicSharedMemorySize, SM_TOT);

    k_zero<<<(NUM_NODES * WIDTH + 255) / 256, 256>>>(out, NUM_NODES * WIDTH);
    k_zero_cnt<<<(NUM_NODES + 255) / 256, 256>>>();
    k_hidden<<<(NUM_EDGES * HIDDEN + 255) / 256, 256>>>(ea, W1, b1);
    k_prep_w2<<<(PLANES * WIDTH * WIDTH + 255) / 256, 256>>>(W2, b2);

    // edge sort-by-sender
    k_count<<<(NUM_EDGES + 255) / 256, 256>>>(snd);
    k_scan<<<1, 1024>>>();
    k_fill<<<(NUM_EDGES + 255) / 256, 256>>>(snd);

    k_gmat_hmma<<<(NUM_NODES + 127) / 128, 256, SM_TOT>>>(x);

    k_msg<<<NUM_EDGES / 8, 256>>>(snd, rcv, out);
}

// round 10
// speedup vs baseline: 1.3892x; 1.3892x over previous
#include <cuda_runtime.h>
#include <cuda_bf16.h>
#include <cstdint>

// Problem constants (fixed by the dataset)
#define NUM_NODES 20000
#define NUM_EDGES 65536
#define WIDTH     64
#define EDGE_FEAT 6
#define HIDDEN    128

// Scratch (allocation-free rule: __device__ globals)
__device__ float g_h [(size_t)NUM_EDGES * HIDDEN];                 // 33.5 MB (SORTED edge order)
__device__ float g_g [(size_t)NUM_NODES * HIDDEN * WIDTH];         // 655 MB  g[n][k][v]
__device__ float g_xb[(size_t)NUM_NODES * WIDTH];                  // 5.1 MB
__device__ __nv_bfloat16 g_wt_hi[(size_t)HIDDEN * WIDTH * WIDTH];  // 2 MB  Wt[k][v][w] hi
__device__ __nv_bfloat16 g_wt_lo[(size_t)HIDDEN * WIDTH * WIDTH];  // 2 MB  Wt[k][v][w] lo
// edge sort-by-sender
__device__ int g_cnt [NUM_NODES];
__device__ int g_off [NUM_NODES + 1];
__device__ int g_inv [NUM_EDGES];     // original edge e -> sorted position
__device__ int g_ssnd[NUM_EDGES];     // sorted senders
__device__ int g_srcv[NUM_EDGES];     // sorted receivers

__device__ __forceinline__ void split_bf16(float a, unsigned short& hi, unsigned short& lo) {
    __nv_bfloat16 h = __float2bfloat16_rn(a);
    float r = a - __bfloat162float(h);
    __nv_bfloat16 l = __float2bfloat16_rn(r);
    hi = __bfloat16_as_ushort(h);
    lo = __bfloat16_as_ushort(l);
}

// Warp-level bf16 MMA (sm_80 PTX feature set — valid for plain sm_103 target)
#define MMA_BF16(c, a, b0, b1) \
    asm volatile("mma.sync.aligned.m16n8k16.row.col.f32.bf16.bf16.f32 " \
        "{%0,%1,%2,%3}, {%4,%5,%6,%7}, {%8,%9}, {%0,%1,%2,%3};" \
        : "+f"((c)[0]), "+f"((c)[1]), "+f"((c)[2]), "+f"((c)[3]) \
        : "r"((a)[0]), "r"((a)[1]), "r"((a)[2]), "r"((a)[3]), "r"(b0), "r"(b1))

// ---------------------------------------------------------------------------
// Zero kernels
// ---------------------------------------------------------------------------
__global__ void k_zero(float* __restrict__ out, int n) {
    int i = blockIdx.x * blockDim.x + threadIdx.x;
    if (i < n) out[i] = 0.f;
}
__global__ void k_zero_cnt() {
    int i = blockIdx.x * blockDim.x + threadIdx.x;
    if (i < NUM_NODES) g_cnt[i] = 0;
}

// ---------------------------------------------------------------------------
// Edge sort-by-sender: count -> scan (1 block) -> fill (perm/inv/sorted arrays)
// ---------------------------------------------------------------------------
__global__ void k_count(const int* __restrict__ snd) {
    int i = blockIdx.x * blockDim.x + threadIdx.x;
    if (i < NUM_EDGES) atomicAdd(&g_cnt[snd[i]], 1);
}
__global__ __launch_bounds__(1024) void k_scan() {
    __shared__ int ps[1024];
    const int tid = threadIdx.x;
    const int CH  = (NUM_NODES + 1023) / 1024;   // 20
    const int base = tid * CH;
    int s = 0;
    for (int j = 0; j < CH; j++) {
        int i = base + j;
        if (i < NUM_NODES) s += g_cnt[i];
    }
    ps[tid] = s;
    __syncthreads();
    for (int d = 1; d < 1024; d <<= 1) {         // Hillis-Steele inclusive scan
        int v = (tid >= d) ? ps[tid - d] : 0;
        __syncthreads();
        ps[tid] += v;
        __syncthreads();
    }
    int run = ps[tid] - s;                        // exclusive prefix of chunk
    for (int j = 0; j < CH; j++) {
        int i = base + j;
        if (i < NUM_NODES) { g_off[i] = run; run += g_cnt[i]; g_cnt[i] = 0; }
    }
    if (tid == 1023) g_off[NUM_NODES] = run;
}
__global__ void k_fill(const int* __restrict__ snd, const int* __restrict__ rcv) {
    int i = blockIdx.x * blockDim.x + threadIdx.x;
    if (i >= NUM_EDGES) return;
    int s = snd[i];
    int pos = g_off[s] + atomicAdd(&g_cnt[s], 1);
    g_inv[i]     = pos;
    g_ssnd[pos]  = s;
    g_srcv[pos]  = rcv[i];
}

// ---------------------------------------------------------------------------
// h[pos][k] = relu( sum_f edge_attr[e][f]*W1[f][k] + b1[k] ), pos = g_inv[e]
// (h written directly in sorted edge order; rows are contiguous 512B)
// ---------------------------------------------------------------------------
__global__ void k_hidden(const float* __restrict__ ea,
                         const float* __restrict__ W1,
                         const float* __restrict__ b1) {
    int idx = blockIdx.x * blockDim.x + threadIdx.x;
    if (idx >= NUM_EDGES * HIDDEN) return;
    int e = idx >> 7;
    int j = idx & (HIDDEN - 1);
    const float* a = ea + (size_t)e * EDGE_FEAT;
    float s = __ldg(b1 + j);
    #pragma unroll
    for (int f = 0; f < EDGE_FEAT; f++)
        s = fmaf(__ldg(a + f), __ldg(W1 + f * HIDDEN + j), s);
    g_h[(size_t)g_inv[e] * HIDDEN + j] = fmaxf(s, 0.f);
}

// ---------------------------------------------------------------------------
// Wt[k][v][w] = W2[k][w*64+v], split bf16 hi/lo (col-major B for mma.row.col)
// ---------------------------------------------------------------------------
__global__ void k_prep_w2(const float* __restrict__ W2) {
    int idx = blockIdx.x * blockDim.x + threadIdx.x;
    if (idx >= HIDDEN * WIDTH * WIDTH) return;
    int k = idx >> 12, rem = idx & 4095, v = rem >> 6, w = rem & 63;
    float val = W2[(size_t)k * 4096 + w * 64 + v];
    unsigned short hi, lo;
    split_bf16(val, hi, lo);
    g_wt_hi[idx] = __ushort_as_bfloat16(hi);
    g_wt_lo[idx] = __ushort_as_bfloat16(lo);
}

// ---------------------------------------------------------------------------
// xb[n][v] = sum_w x[n][w]*b2[w*64+v].  16 nodes/block, thread = (n_local, v4):
// 4 outputs per thread via float4 b2 reads -> 4 FMA per 2 LDS, FMA-bound.
// ---------------------------------------------------------------------------
__global__ __launch_bounds__(256) void k_xb(const float* __restrict__ x,
                                            const float* __restrict__ b2) {
    __shared__ float b2s[WIDTH * WIDTH];       // 16 KB, [w][v]
    __shared__ float xs[16][WIDTH + 1];        // 16 node rows, padded
    const int t = threadIdx.x;
    for (int i = t; i < WIDTH * WIDTH; i += 256)
        b2s[i] = b2[i];
    {   // stage 16 x rows coalesced: 1024 floats
        const int n0 = blockIdx.x * 16;
        for (int i = t; i < 16 * WIDTH; i += 256) {
            int nl = i >> 6, w = i & 63;
            int n = n0 + nl;
            xs[nl][w] = (n < NUM_NODES) ? x[(size_t)n * WIDTH + w] : 0.f;
        }
    }
    __syncthreads();

    const int nl = t >> 4;                     // node within block: 0..15
    const int v4 = t & 15;                     // float4 group: v = v4*4..+3
    float4 acc = make_float4(0.f, 0.f, 0.f, 0.f);
    #pragma unroll 8
    for (int w = 0; w < WIDTH; w++) {
        const float xv = xs[nl][w];
        const float4 b = *(const float4*)&b2s[w * WIDTH + v4 * 4];
        acc.x = fmaf(xv, b.x, acc.x);
        acc.y = fmaf(xv, b.y, acc.y);
        acc.z = fmaf(xv, b.z, acc.z);
        acc.w = fmaf(xv, b.w, acc.w);
    }
    const int n = blockIdx.x * 16 + nl;
    if (n < NUM_NODES)
        *(float4*)(g_xb + (size_t)n * WIDTH + v4 * 4) = acc;
}

// ---------------------------------------------------------------------------
// HMMA g-GEMM (R7-proven version, unchanged): g[n][k][v] = sum_w x[n][w]*Wt[k][v][w]
// CTA = 128-node M-tile; 8 warps (4m x 2n), 32x32 C tile. Split-bf16, A frags
// register-resident across all 128 planes; B register-prefetched.
// ---------------------------------------------------------------------------
#define KP 72
#define SMA_HI 0
#define SMA_LO (128 * KP * 2)                 // 18432
#define SMB_HI (2 * 128 * KP * 2)             // 36864
#define SMB_LO (SMB_HI + 64 * KP * 2)         // 46080
#define SM_TOT (SMB_LO + 64 * KP * 2)         // 55296 bytes

__global__ __launch_bounds__(256) void k_gmat_hmma(const float* __restrict__ x) {
    extern __shared__ char sm[];
    const int t    = threadIdx.x;
    const int lane = t & 31;
    const int warp = t >> 5;
    const int wm   = warp & 3;
    const int wn   = warp >> 2;
    const int n0   = blockIdx.x * 128;
    const int g    = lane >> 2;
    const int l4   = lane & 3;

    // ---- Stage A tile: x rows -> bf16 hi/lo, padded KP-stride rows ----
    {
        const int row  = t >> 1;
        const int half = t & 1;
        const int n    = n0 + row;
        float4 f4[8];
        if (n < NUM_NODES) {
            const float4* xr = (const float4*)(x + (size_t)n * WIDTH) + half * 8;
            #pragma unroll
            for (int j = 0; j < 8; j++) f4[j] = xr[j];
        } else {
            #pragma unroll
            for (int j = 0; j < 8; j++) f4[j] = make_float4(0.f, 0.f, 0.f, 0.f);
        }
        const float* f = (const float*)f4;
        #pragma unroll
        for (int c = 0; c < 4; c++) {
            uint32_t hw[4], lw[4];
            #pragma unroll
            for (int j = 0; j < 4; j++) {
                unsigned short h0, l0, h1, l1;
                split_bf16(f[c * 8 + j * 2 + 0], h0, l0);
                split_bf16(f[c * 8 + j * 2 + 1], h1, l1);
                hw[j] = (uint32_t)h0 | ((uint32_t)h1 << 16);
                lw[j] = (uint32_t)l0 | ((uint32_t)l1 << 16);
            }
            const uint32_t off = (uint32_t)row * (KP * 2) + half * 64 + c * 16;
            *(uint4*)(sm + SMA_HI + off) = make_uint4(hw[0], hw[1], hw[2], hw[3]);
            *(uint4*)(sm + SMA_LO + off) = make_uint4(lw[0], lw[1], lw[2], lw[3]);
        }
    }

    // ---- Stage B plane 0 into smem (padded) ----
    const uint4* wh4 = (const uint4*)g_wt_hi;
    const uint4* wl4 = (const uint4*)g_wt_lo;
    uint4 ph0 = wh4[t], ph1 = wh4[t + 256];
    uint4 pl0 = wl4[t], pl1 = wl4[t + 256];
    {
        const int i0 = t, i1 = t + 256;
        *(uint4*)(sm + SMB_HI + (i0 >> 3) * (KP * 2) + (i0 & 7) * 16) = ph0;
        *(uint4*)(sm + SMB_HI + (i1 >> 3) * (KP * 2) + (i1 & 7) * 16) = ph1;
        *(uint4*)(sm + SMB_LO + (i0 >> 3) * (KP * 2) + (i0 & 7) * 16) = pl0;
        *(uint4*)(sm + SMB_LO + (i1 >> 3) * (KP * 2) + (i1 & 7) * 16) = pl1;
    }
    __syncthreads();

    // ---- Load A fragments once (reused for all 128 k-planes) ----
    uint32_t Ah[2][4][4], Al[2][4][4];
    #pragma unroll
    for (int mt = 0; mt < 2; mt++) {
        #pragma unroll
        for (int kt = 0; kt < 4; kt++) {
            const int r0 = wm * 32 + mt * 16 + g;
            const int cb = kt * 16 + l4 * 2;
            Ah[mt][kt][0] = *(const uint32_t*)(sm + SMA_HI + ((size_t)r0 * KP + cb) * 2);
            Ah[mt][kt][1] = *(const uint32_t*)(sm + SMA_HI + ((size_t)(r0 + 8) * KP + cb) * 2);
            Ah[mt][kt][2] = *(const uint32_t*)(sm + SMA_HI + ((size_t)r0 * KP + cb + 8) * 2);
            Ah[mt][kt][3] = *(const uint32_t*)(sm + SMA_HI + ((size_t)(r0 + 8) * KP + cb + 8) * 2);
            Al[mt][kt][0] = *(const uint32_t*)(sm + SMA_LO + ((size_t)r0 * KP + cb) * 2);
            Al[mt][kt][1] = *(const uint32_t*)(sm + SMA_LO + ((size_t)(r0 + 8) * KP + cb) * 2);
            Al[mt][kt][2] = *(const uint32_t*)(sm + SMA_LO + ((size_t)r0 * KP + cb + 8) * 2);
            Al[mt][kt][3] = *(const uint32_t*)(sm + SMA_LO + ((size_t)(r0 + 8) * KP + cb + 8) * 2);
        }
    }

    // ---- Plane loop: compute 128x64 C per k, store, prefetch next B ----
    for (int k = 0; k < HIDDEN; k++) {
        if (k + 1 < HIDDEN) {
            const size_t base = (size_t)(k + 1) * 512;
            ph0 = wh4[base + t];  ph1 = wh4[base + t + 256];
            pl0 = wl4[base + t];  pl1 = wl4[base + t + 256];
        }

        float C[2][4][4];
        #pragma unroll
        for (int mt = 0; mt < 2; mt++)
            #pragma unroll
            for (int nt = 0; nt < 4; nt++)
                #pragma unroll
                for (int i = 0; i < 4; i++) C[mt][nt][i] = 0.f;

        #pragma unroll
        for (int kt = 0; kt < 4; kt++) {
            #pragma unroll
            for (int nt = 0; nt < 4; nt++) {
                const uint32_t boff =
                    ((uint32_t)(wn * 32 + nt * 8 + g) * KP + kt * 16 + l4 * 2) * 2;
                const uint32_t bh0 = *(const uint32_t*)(sm + SMB_HI + boff);
                const uint32_t bh1 = *(const uint32_t*)(sm + SMB_HI + boff + 16);
                const uint32_t bl0 = *(const uint32_t*)(sm + SMB_LO + boff);
                const uint32_t bl1 = *(const uint32_t*)(sm + SMB_LO + boff + 16);
                #pragma unroll
                for (int mt = 0; mt < 2; mt++) {
                    MMA_BF16(C[mt][nt], Ah[mt][kt], bh0, bh1);
                    MMA_BF16(C[mt][nt], Ah[mt][kt], bl0, bl1);
                    MMA_BF16(C[mt][nt], Al[mt][kt], bh0, bh1);
                }
            }
        }

        #pragma unroll
        for (int mt = 0; mt < 2; mt++) {
            const int n1 = n0 + wm * 32 + mt * 16 + g;
            const int n2 = n1 + 8;
            #pragma unroll
            for (int nt = 0; nt < 4; nt++) {
                const int col = wn * 32 + nt * 8 + l4 * 2;
                if (n1 < NUM_NODES)
                    *(float2*)(g_g + ((size_t)n1 * HIDDEN + k) * WIDTH + col) =
                        make_float2(C[mt][nt][0], C[mt][nt][1]);
                if (n2 < NUM_NODES)
                    *(float2*)(g_g + ((size_t)n2 * HIDDEN + k) * WIDTH + col) =
                        make_float2(C[mt][nt][2], C[mt][nt][3]);
            }
        }

        __syncthreads();
        if (k + 1 < HIDDEN) {
            const int i0 = t, i1 = t + 256;
            *(uint4*)(sm + SMB_HI + (i0 >> 3) * (KP * 2) + (i0 & 7) * 16) = ph0;
            *(uint4*)(sm + SMB_HI + (i1 >> 3) * (KP * 2) + (i1 & 7) * 16) = ph1;
            *(uint4*)(sm + SMB_LO + (i0 >> 3) * (KP * 2) + (i0 & 7) * 16) = pl0;
            *(uint4*)(sm + SMB_LO + (i1 >> 3) * (KP * 2) + (i1 & 7) * 16) = pl1;
            __syncthreads();
        }
    }
}

// ---------------------------------------------------------------------------
// Per sorted edge i: msg[v] = sum_k h[i][k]*g[s][k][v] + xb[s][v];
// atomicAdd into out[r][v]. Warp per edge. h/ssnd/srcv are sequential;
// g gathers have sender locality (avg 3.3 edges/sender -> L2 hits).
// ---------------------------------------------------------------------------
__global__ __launch_bounds__(256) void k_msg(float* __restrict__ out) {
    __shared__ float hs[8][HIDDEN];
    const int wi   = threadIdx.x >> 5;
    const int lane = threadIdx.x & 31;
    const int i    = blockIdx.x * 8 + wi;
    if (i >= NUM_EDGES) return;

    #pragma unroll
    for (int j = 0; j < HIDDEN / 32; j++)
        hs[wi][j * 32 + lane] = g_h[(size_t)i * HIDDEN + j * 32 + lane];
    __syncwarp();

    const int s = g_ssnd[i];
    const int r = g_srcv[i];

    const float2* gp = (const float2*)(g_g + (size_t)s * HIDDEN * WIDTH) + lane;
    float2 acc = ((const float2*)(g_xb + (size_t)s * WIDTH))[lane];

    #pragma unroll 8
    for (int k = 0; k < HIDDEN; k++) {
        float hk = hs[wi][k];
        if (hk != 0.f) {
            float2 gv = gp[k * 32];
            acc.x = fmaf(hk, gv.x, acc.x);
            acc.y = fmaf(hk, gv.y, acc.y);
        }
    }

    atomicAdd(out + (size_t)r * WIDTH + 2 * lane,     acc.x);
    atomicAdd(out + (size_t)r * WIDTH + 2 * lane + 1, acc.y);
}

// ---------------------------------------------------------------------------
// Launch chain (default stream, sequential deps)
// ---------------------------------------------------------------------------
extern "C" void kernel_launch(void* const* d_in, const int* in_sizes, int n_in,
                              void* d_out, int out_size) {
    const float* x   = (const float*)d_in[0];
    const float* ea  = (const float*)d_in[1];
    const float* W1  = (const float*)d_in[2];
    const float* b1  = (const float*)d_in[3];
    const float* W2  = (const float*)d_in[4];
    const float* b2  = (const float*)d_in[5];
    const int*   snd = (const int*)d_in[6];
    const int*   rcv = (const int*)d_in[7];
    float* out = (float*)d_out;

    cudaFuncSetAttribute(k_gmat_hmma, cudaFuncAttributeMaxDynamicSharedMemorySize, SM_TOT);

    k_zero<<<(NUM_NODES * WIDTH + 255) / 256, 256>>>(out, NUM_NODES * WIDTH);
    k_zero_cnt<<<(NUM_NODES + 255) / 256, 256>>>();

    // edge sort-by-sender (perm/inv/sorted snd+rcv)
    k_count<<<(NUM_EDGES + 255) / 256, 256>>>(snd);
    k_scan<<<1, 1024>>>();
    k_fill<<<(NUM_EDGES + 255) / 256, 256>>>(snd, rcv);

    k_hidden<<<(NUM_EDGES * HIDDEN + 255) / 256, 256>>>(ea, W1, b1);
    k_prep_w2<<<(HIDDEN * WIDTH * WIDTH + 255) / 256, 256>>>(W2);
    k_xb<<<(NUM_NODES + 15) / 16, 256>>>(x, b2);

    k_gmat_hmma<<<(NUM_NODES + 127) / 128, 256, SM_TOT>>>(x);

    k_msg<<<NUM_EDGES / 8, 256>>>(out);
}

// round 11
// speedup vs baseline: 1.6816x; 1.2105x over previous
#include <cuda_runtime.h>
#include <cuda_bf16.h>
#include <cstdint>

// Problem constants (fixed by the dataset)
#define NUM_NODES 20000
#define NUM_EDGES 65536
#define WIDTH     64
#define EDGE_FEAT 6
#define HIDDEN    128

// Scratch (allocation-free rule: __device__ globals)
__device__ float g_h [(size_t)NUM_EDGES * HIDDEN];                 // 33.5 MB (SORTED edge order)
__device__ float g_g [(size_t)NUM_NODES * HIDDEN * WIDTH];         // 655 MB  g[n][k][v]
__device__ float g_xb[(size_t)NUM_NODES * WIDTH];                  // 5.1 MB
__device__ __nv_bfloat16 g_wt_hi[(size_t)HIDDEN * WIDTH * WIDTH];  // 2 MB  Wt[k][v][w] hi
__device__ __nv_bfloat16 g_wt_lo[(size_t)HIDDEN * WIDTH * WIDTH];  // 2 MB  Wt[k][v][w] lo
// edge sort-by-sender
__device__ int g_cnt [NUM_NODES];
__device__ int g_off [NUM_NODES + 1];
__device__ int g_inv [NUM_EDGES];     // original edge e -> sorted position
__device__ int g_ssnd[NUM_EDGES];     // sorted senders
__device__ int g_srcv[NUM_EDGES];     // sorted receivers

__device__ __forceinline__ void split_bf16(float a, unsigned short& hi, unsigned short& lo) {
    __nv_bfloat16 h = __float2bfloat16_rn(a);
    float r = a - __bfloat162float(h);
    __nv_bfloat16 l = __float2bfloat16_rn(r);
    hi = __bfloat16_as_ushort(h);
    lo = __bfloat16_as_ushort(l);
}

// Warp-level bf16 MMA (sm_80 PTX feature set — valid for plain sm_103 target)
#define MMA_BF16(c, a, b0, b1) \
    asm volatile("mma.sync.aligned.m16n8k16.row.col.f32.bf16.bf16.f32 " \
        "{%0,%1,%2,%3}, {%4,%5,%6,%7}, {%8,%9}, {%0,%1,%2,%3};" \
        : "+f"((c)[0]), "+f"((c)[1]), "+f"((c)[2]), "+f"((c)[3]) \
        : "r"((a)[0]), "r"((a)[1]), "r"((a)[2]), "r"((a)[3]), "r"(b0), "r"(b1))

// ---------------------------------------------------------------------------
// Zero kernels
// ---------------------------------------------------------------------------
__global__ void k_zero(float* __restrict__ out, int n) {
    int i = blockIdx.x * blockDim.x + threadIdx.x;
    if (i < n) out[i] = 0.f;
}
__global__ void k_zero_cnt() {
    int i = blockIdx.x * blockDim.x + threadIdx.x;
    if (i < NUM_NODES) g_cnt[i] = 0;
}

// ---------------------------------------------------------------------------
// Edge sort-by-sender: count -> scan (1 block) -> fill (inv/sorted arrays)
// ---------------------------------------------------------------------------
__global__ void k_count(const int* __restrict__ snd) {
    int i = blockIdx.x * blockDim.x + threadIdx.x;
    if (i < NUM_EDGES) atomicAdd(&g_cnt[snd[i]], 1);
}
__global__ __launch_bounds__(1024) void k_scan() {
    __shared__ int ps[1024];
    const int tid = threadIdx.x;
    const int CH  = (NUM_NODES + 1023) / 1024;   // 20
    const int base = tid * CH;
    int s = 0;
    #pragma unroll
    for (int j = 0; j < CH; j++) {
        int i = base + j;
        if (i < NUM_NODES) s += g_cnt[i];
    }
    ps[tid] = s;
    __syncthreads();
    for (int d = 1; d < 1024; d <<= 1) {         // Hillis-Steele inclusive scan
        int v = (tid >= d) ? ps[tid - d] : 0;
        __syncthreads();
        ps[tid] += v;
        __syncthreads();
    }
    int run = ps[tid] - s;                        // exclusive prefix of chunk
    #pragma unroll
    for (int j = 0; j < CH; j++) {
        int i = base + j;
        if (i < NUM_NODES) { g_off[i] = run; run += g_cnt[i]; g_cnt[i] = 0; }
    }
    if (tid == 1023) g_off[NUM_NODES] = run;
}
__global__ void k_fill(const int* __restrict__ snd, const int* __restrict__ rcv) {
    int i = blockIdx.x * blockDim.x + threadIdx.x;
    if (i >= NUM_EDGES) return;
    int s = snd[i];
    int pos = g_off[s] + atomicAdd(&g_cnt[s], 1);
    g_inv[i]     = pos;
    g_ssnd[pos]  = s;
    g_srcv[pos]  = rcv[i];
}

// ---------------------------------------------------------------------------
// h[pos][k] = relu( sum_f edge_attr[e][f]*W1[f][k] + b1[k] ), pos = g_inv[e]
// ---------------------------------------------------------------------------
__global__ void k_hidden(const float* __restrict__ ea,
                         const float* __restrict__ W1,
                         const float* __restrict__ b1) {
    int idx = blockIdx.x * blockDim.x + threadIdx.x;
    if (idx >= NUM_EDGES * HIDDEN) return;
    int e = idx >> 7;
    int j = idx & (HIDDEN - 1);
    const float* a = ea + (size_t)e * EDGE_FEAT;
    float s = __ldg(b1 + j);
    #pragma unroll
    for (int f = 0; f < EDGE_FEAT; f++)
        s = fmaf(__ldg(a + f), __ldg(W1 + f * HIDDEN + j), s);
    g_h[(size_t)g_inv[e] * HIDDEN + j] = fmaxf(s, 0.f);
}

// ---------------------------------------------------------------------------
// Wt[k][v][w] = W2[k][w*64+v], split bf16 hi/lo (col-major B for mma.row.col)
// ---------------------------------------------------------------------------
__global__ void k_prep_w2(const float* __restrict__ W2) {
    int idx = blockIdx.x * blockDim.x + threadIdx.x;
    if (idx >= HIDDEN * WIDTH * WIDTH) return;
    int k = idx >> 12, rem = idx & 4095, v = rem >> 6, w = rem & 63;
    float val = W2[(size_t)k * 4096 + w * 64 + v];
    unsigned short hi, lo;
    split_bf16(val, hi, lo);
    g_wt_hi[idx] = __ushort_as_bfloat16(hi);
    g_wt_lo[idx] = __ushort_as_bfloat16(lo);
}

// ---------------------------------------------------------------------------
// xb[n][v] = sum_w x[n][w]*b2[w*64+v].  16 nodes/block, 4 outputs/thread.
// ---------------------------------------------------------------------------
__global__ __launch_bounds__(256) void k_xb(const float* __restrict__ x,
                                            const float* __restrict__ b2) {
    __shared__ float b2s[WIDTH * WIDTH];       // 16 KB, [w][v]
    __shared__ float xs[16][WIDTH + 1];        // 16 node rows, padded
    const int t = threadIdx.x;
    for (int i = t; i < WIDTH * WIDTH; i += 256)
        b2s[i] = b2[i];
    {
        const int n0 = blockIdx.x * 16;
        for (int i = t; i < 16 * WIDTH; i += 256) {
            int nl = i >> 6, w = i & 63;
            int n = n0 + nl;
            xs[nl][w] = (n < NUM_NODES) ? x[(size_t)n * WIDTH + w] : 0.f;
        }
    }
    __syncthreads();

    const int nl = t >> 4;
    const int v4 = t & 15;
    float4 acc = make_float4(0.f, 0.f, 0.f, 0.f);
    #pragma unroll 8
    for (int w = 0; w < WIDTH; w++) {
        const float xv = xs[nl][w];
        const float4 b = *(const float4*)&b2s[w * WIDTH + v4 * 4];
        acc.x = fmaf(xv, b.x, acc.x);
        acc.y = fmaf(xv, b.y, acc.y);
        acc.z = fmaf(xv, b.z, acc.z);
        acc.w = fmaf(xv, b.w, acc.w);
    }
    const int n = blockIdx.x * 16 + nl;
    if (n < NUM_NODES)
        *(float4*)(g_xb + (size_t)n * WIDTH + v4 * 4) = acc;
}

// ---------------------------------------------------------------------------
// HMMA g-GEMM: g[n][k][v] = sum_w x[n][w]*Wt[k][v][w]
// CTA = 128-node M-tile; 8 warps (4m x 2n), 32x32 C tile. Split-bf16, A frags
// register-resident across all 128 planes; B register-prefetched into a
// DOUBLE-buffered smem B (STS targets the idle buffer -> ONE barrier/plane).
// ---------------------------------------------------------------------------
#define KP 72
#define SMA_HI 0
#define SMA_LO (128 * KP * 2)                  // 18432
#define SMB_BASE (2 * 128 * KP * 2)            // 36864
#define SMB(p, hl) (SMB_BASE + (p) * 18432 + (hl) * 9216)
#define SM_TOT (SMB_BASE + 2 * 18432)          // 73728 bytes

__global__ __launch_bounds__(256) void k_gmat_hmma(const float* __restrict__ x) {
    extern __shared__ char sm[];
    const int t    = threadIdx.x;
    const int lane = t & 31;
    const int warp = t >> 5;
    const int wm   = warp & 3;
    const int wn   = warp >> 2;
    const int n0   = blockIdx.x * 128;
    const int g    = lane >> 2;
    const int l4   = lane & 3;

    // ---- Stage A tile: x rows -> bf16 hi/lo, padded KP-stride rows ----
    {
        const int row  = t >> 1;
        const int half = t & 1;
        const int n    = n0 + row;
        float4 f4[8];
        if (n < NUM_NODES) {
            const float4* xr = (const float4*)(x + (size_t)n * WIDTH) + half * 8;
            #pragma unroll
            for (int j = 0; j < 8; j++) f4[j] = xr[j];
        } else {
            #pragma unroll
            for (int j = 0; j < 8; j++) f4[j] = make_float4(0.f, 0.f, 0.f, 0.f);
        }
        const float* f = (const float*)f4;
        #pragma unroll
        for (int c = 0; c < 4; c++) {
            uint32_t hw[4], lw[4];
            #pragma unroll
            for (int j = 0; j < 4; j++) {
                unsigned short h0, l0, h1, l1;
                split_bf16(f[c * 8 + j * 2 + 0], h0, l0);
                split_bf16(f[c * 8 + j * 2 + 1], h1, l1);
                hw[j] = (uint32_t)h0 | ((uint32_t)h1 << 16);
                lw[j] = (uint32_t)l0 | ((uint32_t)l1 << 16);
            }
            const uint32_t off = (uint32_t)row * (KP * 2) + half * 64 + c * 16;
            *(uint4*)(sm + SMA_HI + off) = make_uint4(hw[0], hw[1], hw[2], hw[3]);
            *(uint4*)(sm + SMA_LO + off) = make_uint4(lw[0], lw[1], lw[2], lw[3]);
        }
    }

    const uint4* wh4 = (const uint4*)g_wt_hi;
    const uint4* wl4 = (const uint4*)g_wt_lo;
    const int i0 = t, i1 = t + 256;
    const uint32_t so0 = (uint32_t)(i0 >> 3) * (KP * 2) + (i0 & 7) * 16;
    const uint32_t so1 = (uint32_t)(i1 >> 3) * (KP * 2) + (i1 & 7) * 16;

    // ---- Stage B plane 0 into buffer 0 ----
    {
        uint4 a0 = wh4[i0], a1 = wh4[i1], b0 = wl4[i0], b1 = wl4[i1];
        *(uint4*)(sm + SMB(0, 0) + so0) = a0;
        *(uint4*)(sm + SMB(0, 0) + so1) = a1;
        *(uint4*)(sm + SMB(0, 1) + so0) = b0;
        *(uint4*)(sm + SMB(0, 1) + so1) = b1;
    }
    __syncthreads();   // A tile + B plane 0 visible

    // ---- Load A fragments once (reused for all 128 k-planes) ----
    uint32_t Ah[2][4][4], Al[2][4][4];
    #pragma unroll
    for (int mt = 0; mt < 2; mt++) {
        #pragma unroll
        for (int kt = 0; kt < 4; kt++) {
            const int r0 = wm * 32 + mt * 16 + g;
            const int cb = kt * 16 + l4 * 2;
            Ah[mt][kt][0] = *(const uint32_t*)(sm + SMA_HI + ((size_t)r0 * KP + cb) * 2);
            Ah[mt][kt][1] = *(const uint32_t*)(sm + SMA_HI + ((size_t)(r0 + 8) * KP + cb) * 2);
            Ah[mt][kt][2] = *(const uint32_t*)(sm + SMA_HI + ((size_t)r0 * KP + cb + 8) * 2);
            Ah[mt][kt][3] = *(const uint32_t*)(sm + SMA_HI + ((size_t)(r0 + 8) * KP + cb + 8) * 2);
            Al[mt][kt][0] = *(const uint32_t*)(sm + SMA_LO + ((size_t)r0 * KP + cb) * 2);
            Al[mt][kt][1] = *(const uint32_t*)(sm + SMA_LO + ((size_t)(r0 + 8) * KP + cb) * 2);
            Al[mt][kt][2] = *(const uint32_t*)(sm + SMA_LO + ((size_t)r0 * KP + cb + 8) * 2);
            Al[mt][kt][3] = *(const uint32_t*)(sm + SMA_LO + ((size_t)(r0 + 8) * KP + cb + 8) * 2);
        }
    }

    // ---- Plane loop: compute from buf p; prefetch k+1 via regs -> buf p^1;
    //      ONE __syncthreads per plane (STS targets idle buffer). ----
    for (int k = 0; k < HIDDEN; k++) {
        const int p = k & 1;
        uint4 ph0, ph1, pl0, pl1;
        const bool pre = (k + 1 < HIDDEN);
        if (pre) {                        // issue LDGs early; MMAs hide latency
            const size_t base = (size_t)(k + 1) * 512;
            ph0 = wh4[base + i0];  ph1 = wh4[base + i1];
            pl0 = wl4[base + i0];  pl1 = wl4[base + i1];
        }

        float C[2][4][4];
        #pragma unroll
        for (int mt = 0; mt < 2; mt++)
            #pragma unroll
            for (int nt = 0; nt < 4; nt++)
                #pragma unroll
                for (int i = 0; i < 4; i++) C[mt][nt][i] = 0.f;

        #pragma unroll
        for (int kt = 0; kt < 4; kt++) {
            #pragma unroll
            for (int nt = 0; nt < 4; nt++) {
                const uint32_t boff =
                    ((uint32_t)(wn * 32 + nt * 8 + g) * KP + kt * 16 + l4 * 2) * 2;
                const uint32_t bh0 = *(const uint32_t*)(sm + SMB(p, 0) + boff);
                const uint32_t bh1 = *(const uint32_t*)(sm + SMB(p, 0) + boff + 16);
                const uint32_t bl0 = *(const uint32_t*)(sm + SMB(p, 1) + boff);
                const uint32_t bl1 = *(const uint32_t*)(sm + SMB(p, 1) + boff + 16);
                #pragma unroll
                for (int mt = 0; mt < 2; mt++) {
                    MMA_BF16(C[mt][nt], Ah[mt][kt], bh0, bh1);
                    MMA_BF16(C[mt][nt], Ah[mt][kt], bl0, bl1);
                    MMA_BF16(C[mt][nt], Al[mt][kt], bh0, bh1);
                }
            }
        }

        if (pre) {                        // STS into the idle buffer (no race)
            *(uint4*)(sm + SMB(p ^ 1, 0) + so0) = ph0;
            *(uint4*)(sm + SMB(p ^ 1, 0) + so1) = ph1;
            *(uint4*)(sm + SMB(p ^ 1, 1) + so0) = pl0;
            *(uint4*)(sm + SMB(p ^ 1, 1) + so1) = pl1;
        }

        #pragma unroll
        for (int mt = 0; mt < 2; mt++) {
            const int n1 = n0 + wm * 32 + mt * 16 + g;
            const int n2 = n1 + 8;
            #pragma unroll
            for (int nt = 0; nt < 4; nt++) {
                const int col = wn * 32 + nt * 8 + l4 * 2;
                if (n1 < NUM_NODES)
                    *(float2*)(g_g + ((size_t)n1 * HIDDEN + k) * WIDTH + col) =
                        make_float2(C[mt][nt][0], C[mt][nt][1]);
                if (n2 < NUM_NODES)
                    *(float2*)(g_g + ((size_t)n2 * HIDDEN + k) * WIDTH + col) =
                        make_float2(C[mt][nt][2], C[mt][nt][3]);
            }
        }

        if (pre) __syncthreads();         // buf p^1 ready; buf p free next plane
    }
}

// ---------------------------------------------------------------------------
// Per sorted edge i: msg[v] = sum_k h[i][k]*g[s][k][v] + xb[s][v];
// atomicAdd into out[r][v]. Warp per edge; relu-sparsity + sender locality.
// ---------------------------------------------------------------------------
__global__ __launch_bounds__(256) void k_msg(float* __restrict__ out) {
    __shared__ float hs[8][HIDDEN];
    const int wi   = threadIdx.x >> 5;
    const int lane = threadIdx.x & 31;
    const int i    = blockIdx.x * 8 + wi;
    if (i >= NUM_EDGES) return;

    #pragma unroll
    for (int j = 0; j < HIDDEN / 32; j++)
        hs[wi][j * 32 + lane] = g_h[(size_t)i * HIDDEN + j * 32 + lane];
    __syncwarp();

    const int s = g_ssnd[i];
    const int r = g_srcv[i];

    const float2* gp = (const float2*)(g_g + (size_t)s * HIDDEN * WIDTH) + lane;
    float2 acc = ((const float2*)(g_xb + (size_t)s * WIDTH))[lane];

    #pragma unroll 8
    for (int k = 0; k < HIDDEN; k++) {
        float hk = hs[wi][k];
        if (hk != 0.f) {
            float2 gv = gp[k * 32];
            acc.x = fmaf(hk, gv.x, acc.x);
            acc.y = fmaf(hk, gv.y, acc.y);
        }
    }

    atomicAdd(out + (size_t)r * WIDTH + 2 * lane,     acc.x);
    atomicAdd(out + (size_t)r * WIDTH + 2 * lane + 1, acc.y);
}

// ---------------------------------------------------------------------------
// Launch: fork-join two streams. Side stream: prep_w2 -> gmat (the long pole).
// Default stream: sort chain + hidden + xb + out-zero (hidden under gmat).
// Streams/events created lazily on the first (non-capture) correctness call.
// ---------------------------------------------------------------------------
extern "C" void kernel_launch(void* const* d_in, const int* in_sizes, int n_in,
                              void* d_out, int out_size) {
    const float* x   = (const float*)d_in[0];
    const float* ea  = (const float*)d_in[1];
    const float* W1  = (const float*)d_in[2];
    const float* b1  = (const float*)d_in[3];
    const float* W2  = (const float*)d_in[4];
    const float* b2  = (const float*)d_in[5];
    const int*   snd = (const int*)d_in[6];
    const int*   rcv = (const int*)d_in[7];
    float* out = (float*)d_out;

    static cudaStream_t s2 = nullptr;
    static cudaEvent_t  evF = nullptr, evJ = nullptr;
    if (!s2) {
        cudaStreamCreateWithFlags(&s2, cudaStreamNonBlocking);
        cudaEventCreateWithFlags(&evF, cudaEventDisableTiming);
        cudaEventCreateWithFlags(&evJ, cudaEventDisableTiming);
        cudaFuncSetAttribute(k_gmat_hmma,
                             cudaFuncAttributeMaxDynamicSharedMemorySize, SM_TOT);
    }

    // ---- fork ----
    cudaEventRecord(evF, 0);
    cudaStreamWaitEvent(s2, evF, 0);

    // side stream: weight prep + the 390us tensor GEMM
    k_prep_w2<<<(HIDDEN * WIDTH * WIDTH + 255) / 256, 256, 0, s2>>>(W2);
    k_gmat_hmma<<<(NUM_NODES + 127) / 128, 256, SM_TOT, s2>>>(x);
    cudaEventRecord(evJ, s2);

    // default stream: everything else (independent of g)
    k_zero_cnt<<<(NUM_NODES + 255) / 256, 256>>>();
    k_count<<<(NUM_EDGES + 255) / 256, 256>>>(snd);
    k_scan<<<1, 1024>>>();
    k_fill<<<(NUM_EDGES + 255) / 256, 256>>>(snd, rcv);
    k_hidden<<<(NUM_EDGES * HIDDEN + 255) / 256, 256>>>(ea, W1, b1);
    k_xb<<<(NUM_NODES + 15) / 16, 256>>>(x, b2);
    k_zero<<<(NUM_NODES * WIDTH + 255) / 256, 256>>>(out, NUM_NODES * WIDTH);

    // ---- join, then the gather/scatter ----
    cudaStreamWaitEvent((cudaStream_t)0, evJ, 0);
    k_msg<<<NUM_EDGES / 8, 256>>>(out);
}

// round 12
// speedup vs baseline: 1.7380x; 1.0335x over previous
#include <cuda_runtime.h>
#include <cuda_bf16.h>
#include <cuda_fp16.h>
#include <cstdint>

// Problem constants (fixed by the dataset)
#define NUM_NODES 20000
#define NUM_EDGES 65536
#define WIDTH     64
#define EDGE_FEAT 6
#define HIDDEN    128

// Scratch (allocation-free rule: __device__ globals)
__device__ float  g_h [(size_t)NUM_EDGES * HIDDEN];                // 33.5 MB (SORTED edge order)
__device__ __half g_gh[(size_t)NUM_NODES * HIDDEN * WIDTH];        // 328 MB  g[n][k][v] fp16
__device__ float  g_xb[(size_t)NUM_NODES * WIDTH];                 // 5.1 MB
__device__ __nv_bfloat16 g_wt_hi[(size_t)HIDDEN * WIDTH * WIDTH];  // 2 MB  Wt[k][v][w] hi
__device__ __nv_bfloat16 g_wt_lo[(size_t)HIDDEN * WIDTH * WIDTH];  // 2 MB  Wt[k][v][w] lo
// edge sort-by-sender
__device__ int g_cnt [NUM_NODES];
__device__ int g_off [NUM_NODES + 1];
__device__ int g_inv [NUM_EDGES];     // original edge e -> sorted position
__device__ int g_ssnd[NUM_EDGES];     // sorted senders
__device__ int g_srcv[NUM_EDGES];     // sorted receivers

__device__ __forceinline__ void split_bf16(float a, unsigned short& hi, unsigned short& lo) {
    __nv_bfloat16 h = __float2bfloat16_rn(a);
    float r = a - __bfloat162float(h);
    __nv_bfloat16 l = __float2bfloat16_rn(r);
    hi = __bfloat16_as_ushort(h);
    lo = __bfloat16_as_ushort(l);
}

// Warp-level bf16 MMA (sm_80 PTX feature set — valid for plain sm_103 target)
#define MMA_BF16(c, a, b0, b1) \
    asm volatile("mma.sync.aligned.m16n8k16.row.col.f32.bf16.bf16.f32 " \
        "{%0,%1,%2,%3}, {%4,%5,%6,%7}, {%8,%9}, {%0,%1,%2,%3};" \
        : "+f"((c)[0]), "+f"((c)[1]), "+f"((c)[2]), "+f"((c)[3]) \
        : "r"((a)[0]), "r"((a)[1]), "r"((a)[2]), "r"((a)[3]), "r"(b0), "r"(b1))

// ---------------------------------------------------------------------------
// Zero kernels
// ---------------------------------------------------------------------------
__global__ void k_zero(float* __restrict__ out, int n) {
    int i = blockIdx.x * blockDim.x + threadIdx.x;
    if (i < n) out[i] = 0.f;
}
__global__ void k_zero_cnt() {
    int i = blockIdx.x * blockDim.x + threadIdx.x;
    if (i < NUM_NODES) g_cnt[i] = 0;
}

// ---------------------------------------------------------------------------
// Edge sort-by-sender: count -> scan (1 block) -> fill (inv/sorted arrays)
// ---------------------------------------------------------------------------
__global__ void k_count(const int* __restrict__ snd) {
    int i = blockIdx.x * blockDim.x + threadIdx.x;
    if (i < NUM_EDGES) atomicAdd(&g_cnt[snd[i]], 1);
}
__global__ __launch_bounds__(1024) void k_scan() {
    __shared__ int ps[1024];
    const int tid = threadIdx.x;
    const int CH  = (NUM_NODES + 1023) / 1024;   // 20
    const int base = tid * CH;
    int s = 0;
    #pragma unroll
    for (int j = 0; j < CH; j++) {
        int i = base + j;
        if (i < NUM_NODES) s += g_cnt[i];
    }
    ps[tid] = s;
    __syncthreads();
    for (int d = 1; d < 1024; d <<= 1) {         // Hillis-Steele inclusive scan
        int v = (tid >= d) ? ps[tid - d] : 0;
        __syncthreads();
        ps[tid] += v;
        __syncthreads();
    }
    int run = ps[tid] - s;                        // exclusive prefix of chunk
    #pragma unroll
    for (int j = 0; j < CH; j++) {
        int i = base + j;
        if (i < NUM_NODES) { g_off[i] = run; run += g_cnt[i]; g_cnt[i] = 0; }
    }
    if (tid == 1023) g_off[NUM_NODES] = run;
}
__global__ void k_fill(const int* __restrict__ snd, const int* __restrict__ rcv) {
    int i = blockIdx.x * blockDim.x + threadIdx.x;
    if (i >= NUM_EDGES) return;
    int s = snd[i];
    int pos = g_off[s] + atomicAdd(&g_cnt[s], 1);
    g_inv[i]     = pos;
    g_ssnd[pos]  = s;
    g_srcv[pos]  = rcv[i];
}

// ---------------------------------------------------------------------------
// h[pos][k] = relu( sum_f edge_attr[e][f]*W1[f][k] + b1[k] ), pos = g_inv[e]
// ---------------------------------------------------------------------------
__global__ void k_hidden(const float* __restrict__ ea,
                         const float* __restrict__ W1,
                         const float* __restrict__ b1) {
    int idx = blockIdx.x * blockDim.x + threadIdx.x;
    if (idx >= NUM_EDGES * HIDDEN) return;
    int e = idx >> 7;
    int j = idx & (HIDDEN - 1);
    const float* a = ea + (size_t)e * EDGE_FEAT;
    float s = __ldg(b1 + j);
    #pragma unroll
    for (int f = 0; f < EDGE_FEAT; f++)
        s = fmaf(__ldg(a + f), __ldg(W1 + f * HIDDEN + j), s);
    g_h[(size_t)g_inv[e] * HIDDEN + j] = fmaxf(s, 0.f);
}

// ---------------------------------------------------------------------------
// Wt[k][v][w] = W2[k][w*64+v], split bf16 hi/lo (col-major B for mma.row.col)
// ---------------------------------------------------------------------------
__global__ void k_prep_w2(const float* __restrict__ W2) {
    int idx = blockIdx.x * blockDim.x + threadIdx.x;
    if (idx >= HIDDEN * WIDTH * WIDTH) return;
    int k = idx >> 12, rem = idx & 4095, v = rem >> 6, w = rem & 63;
    float val = W2[(size_t)k * 4096 + w * 64 + v];
    unsigned short hi, lo;
    split_bf16(val, hi, lo);
    g_wt_hi[idx] = __ushort_as_bfloat16(hi);
    g_wt_lo[idx] = __ushort_as_bfloat16(lo);
}

// ---------------------------------------------------------------------------
// xb[n][v] = sum_w x[n][w]*b2[w*64+v].  16 nodes/block, 4 outputs/thread.
// ---------------------------------------------------------------------------
__global__ __launch_bounds__(256) void k_xb(const float* __restrict__ x,
                                            const float* __restrict__ b2) {
    __shared__ float b2s[WIDTH * WIDTH];       // 16 KB, [w][v]
    __shared__ float xs[16][WIDTH + 1];        // 16 node rows, padded
    const int t = threadIdx.x;
    for (int i = t; i < WIDTH * WIDTH; i += 256)
        b2s[i] = b2[i];
    {
        const int n0 = blockIdx.x * 16;
        for (int i = t; i < 16 * WIDTH; i += 256) {
            int nl = i >> 6, w = i & 63;
            int n = n0 + nl;
            xs[nl][w] = (n < NUM_NODES) ? x[(size_t)n * WIDTH + w] : 0.f;
        }
    }
    __syncthreads();

    const int nl = t >> 4;
    const int v4 = t & 15;
    float4 acc = make_float4(0.f, 0.f, 0.f, 0.f);
    #pragma unroll 8
    for (int w = 0; w < WIDTH; w++) {
        const float xv = xs[nl][w];
        const float4 b = *(const float4*)&b2s[w * WIDTH + v4 * 4];
        acc.x = fmaf(xv, b.x, acc.x);
        acc.y = fmaf(xv, b.y, acc.y);
        acc.z = fmaf(xv, b.z, acc.z);
        acc.w = fmaf(xv, b.w, acc.w);
    }
    const int n = blockIdx.x * 16 + nl;
    if (n < NUM_NODES)
        *(float4*)(g_xb + (size_t)n * WIDTH + v4 * 4) = acc;
}

// ---------------------------------------------------------------------------
// HMMA g-GEMM: g[n][k][v] = sum_w x[n][w]*Wt[k][v][w], stored as fp16.
// CTA = 128-node M-tile; 8 warps (4m x 2n), 32x32 C tile. Split-bf16, A frags
// register-resident across all 128 planes; B register-prefetched into a
// DOUBLE-buffered smem B (STS targets the idle buffer -> ONE barrier/plane).
// ---------------------------------------------------------------------------
#define KP 72
#define SMA_HI 0
#define SMA_LO (128 * KP * 2)                  // 18432
#define SMB_BASE (2 * 128 * KP * 2)            // 36864
#define SMB(p, hl) (SMB_BASE + (p) * 18432 + (hl) * 9216)
#define SM_TOT (SMB_BASE + 2 * 18432)          // 73728 bytes

__global__ __launch_bounds__(256) void k_gmat_hmma(const float* __restrict__ x) {
    extern __shared__ char sm[];
    const int t    = threadIdx.x;
    const int lane = t & 31;
    const int warp = t >> 5;
    const int wm   = warp & 3;
    const int wn   = warp >> 2;
    const int n0   = blockIdx.x * 128;
    const int g    = lane >> 2;
    const int l4   = lane & 3;

    // ---- Stage A tile: x rows -> bf16 hi/lo, padded KP-stride rows ----
    {
        const int row  = t >> 1;
        const int half = t & 1;
        const int n    = n0 + row;
        float4 f4[8];
        if (n < NUM_NODES) {
            const float4* xr = (const float4*)(x + (size_t)n * WIDTH) + half * 8;
            #pragma unroll
            for (int j = 0; j < 8; j++) f4[j] = xr[j];
        } else {
            #pragma unroll
            for (int j = 0; j < 8; j++) f4[j] = make_float4(0.f, 0.f, 0.f, 0.f);
        }
        const float* f = (const float*)f4;
        #pragma unroll
        for (int c = 0; c < 4; c++) {
            uint32_t hw[4], lw[4];
            #pragma unroll
            for (int j = 0; j < 4; j++) {
                unsigned short h0, l0, h1, l1;
                split_bf16(f[c * 8 + j * 2 + 0], h0, l0);
                split_bf16(f[c * 8 + j * 2 + 1], h1, l1);
                hw[j] = (uint32_t)h0 | ((uint32_t)h1 << 16);
                lw[j] = (uint32_t)l0 | ((uint32_t)l1 << 16);
            }
            const uint32_t off = (uint32_t)row * (KP * 2) + half * 64 + c * 16;
            *(uint4*)(sm + SMA_HI + off) = make_uint4(hw[0], hw[1], hw[2], hw[3]);
            *(uint4*)(sm + SMA_LO + off) = make_uint4(lw[0], lw[1], lw[2], lw[3]);
        }
    }

    const uint4* wh4 = (const uint4*)g_wt_hi;
    const uint4* wl4 = (const uint4*)g_wt_lo;
    const int i0 = t, i1 = t + 256;
    const uint32_t so0 = (uint32_t)(i0 >> 3) * (KP * 2) + (i0 & 7) * 16;
    const uint32_t so1 = (uint32_t)(i1 >> 3) * (KP * 2) + (i1 & 7) * 16;

    // ---- Stage B plane 0 into buffer 0 ----
    {
        uint4 a0 = wh4[i0], a1 = wh4[i1], b0 = wl4[i0], b1 = wl4[i1];
        *(uint4*)(sm + SMB(0, 0) + so0) = a0;
        *(uint4*)(sm + SMB(0, 0) + so1) = a1;
        *(uint4*)(sm + SMB(0, 1) + so0) = b0;
        *(uint4*)(sm + SMB(0, 1) + so1) = b1;
    }
    __syncthreads();   // A tile + B plane 0 visible

    // ---- Load A fragments once (reused for all 128 k-planes) ----
    uint32_t Ah[2][4][4], Al[2][4][4];
    #pragma unroll
    for (int mt = 0; mt < 2; mt++) {
        #pragma unroll
        for (int kt = 0; kt < 4; kt++) {
            const int r0 = wm * 32 + mt * 16 + g;
            const int cb = kt * 16 + l4 * 2;
            Ah[mt][kt][0] = *(const uint32_t*)(sm + SMA_HI + ((size_t)r0 * KP + cb) * 2);
            Ah[mt][kt][1] = *(const uint32_t*)(sm + SMA_HI + ((size_t)(r0 + 8) * KP + cb) * 2);
            Ah[mt][kt][2] = *(const uint32_t*)(sm + SMA_HI + ((size_t)r0 * KP + cb + 8) * 2);
            Ah[mt][kt][3] = *(const uint32_t*)(sm + SMA_HI + ((size_t)(r0 + 8) * KP + cb + 8) * 2);
            Al[mt][kt][0] = *(const uint32_t*)(sm + SMA_LO + ((size_t)r0 * KP + cb) * 2);
            Al[mt][kt][1] = *(const uint32_t*)(sm + SMA_LO + ((size_t)(r0 + 8) * KP + cb) * 2);
            Al[mt][kt][2] = *(const uint32_t*)(sm + SMA_LO + ((size_t)r0 * KP + cb + 8) * 2);
            Al[mt][kt][3] = *(const uint32_t*)(sm + SMA_LO + ((size_t)(r0 + 8) * KP + cb + 8) * 2);
        }
    }

    // ---- Plane loop: compute from buf p; prefetch k+1 via regs -> buf p^1;
    //      ONE __syncthreads per plane (STS targets idle buffer). ----
    for (int k = 0; k < HIDDEN; k++) {
        const int p = k & 1;
        uint4 ph0, ph1, pl0, pl1;
        const bool pre = (k + 1 < HIDDEN);
        if (pre) {                        // issue LDGs early; MMAs hide latency
            const size_t base = (size_t)(k + 1) * 512;
            ph0 = wh4[base + i0];  ph1 = wh4[base + i1];
            pl0 = wl4[base + i0];  pl1 = wl4[base + i1];
        }

        float C[2][4][4];
        #pragma unroll
        for (int mt = 0; mt < 2; mt++)
            #pragma unroll
            for (int nt = 0; nt < 4; nt++)
                #pragma unroll
                for (int i = 0; i < 4; i++) C[mt][nt][i] = 0.f;

        #pragma unroll
        for (int kt = 0; kt < 4; kt++) {
            #pragma unroll
            for (int nt = 0; nt < 4; nt++) {
                const uint32_t boff =
                    ((uint32_t)(wn * 32 + nt * 8 + g) * KP + kt * 16 + l4 * 2) * 2;
                const uint32_t bh0 = *(const uint32_t*)(sm + SMB(p, 0) + boff);
                const uint32_t bh1 = *(const uint32_t*)(sm + SMB(p, 0) + boff + 16);
                const uint32_t bl0 = *(const uint32_t*)(sm + SMB(p, 1) + boff);
                const uint32_t bl1 = *(const uint32_t*)(sm + SMB(p, 1) + boff + 16);
                #pragma unroll
                for (int mt = 0; mt < 2; mt++) {
                    MMA_BF16(C[mt][nt], Ah[mt][kt], bh0, bh1);
                    MMA_BF16(C[mt][nt], Ah[mt][kt], bl0, bl1);
                    MMA_BF16(C[mt][nt], Al[mt][kt], bh0, bh1);
                }
            }
        }

        if (pre) {                        // STS into the idle buffer (no race)
            *(uint4*)(sm + SMB(p ^ 1, 0) + so0) = ph0;
            *(uint4*)(sm + SMB(p ^ 1, 0) + so1) = ph1;
            *(uint4*)(sm + SMB(p ^ 1, 1) + so0) = pl0;
            *(uint4*)(sm + SMB(p ^ 1, 1) + so1) = pl1;
        }

        // Store this k-plane as fp16 (halves g DRAM traffic on both sides)
        #pragma unroll
        for (int mt = 0; mt < 2; mt++) {
            const int n1 = n0 + wm * 32 + mt * 16 + g;
            const int n2 = n1 + 8;
            #pragma unroll
            for (int nt = 0; nt < 4; nt++) {
                const int col = wn * 32 + nt * 8 + l4 * 2;
                if (n1 < NUM_NODES)
                    *(__half2*)(g_gh + ((size_t)n1 * HIDDEN + k) * WIDTH + col) =
                        __floats2half2_rn(C[mt][nt][0], C[mt][nt][1]);
                if (n2 < NUM_NODES)
                    *(__half2*)(g_gh + ((size_t)n2 * HIDDEN + k) * WIDTH + col) =
                        __floats2half2_rn(C[mt][nt][2], C[mt][nt][3]);
            }
        }

        if (pre) __syncthreads();         // buf p^1 ready; buf p free next plane
    }
}

// ---------------------------------------------------------------------------
// Per sorted edge i: msg[v] = sum_k h[i][k]*g[s][k][v] + xb[s][v];
// g rows are fp16 (one 128B line per k) -> half the DRAM traffic.
// atomicAdd into out[r][v]. Warp per edge; relu-sparsity + sender locality.
// ---------------------------------------------------------------------------
__global__ __launch_bounds__(256) void k_msg(float* __restrict__ out) {
    __shared__ float hs[8][HIDDEN];
    const int wi   = threadIdx.x >> 5;
    const int lane = threadIdx.x & 31;
    const int i    = blockIdx.x * 8 + wi;
    if (i >= NUM_EDGES) return;

    #pragma unroll
    for (int j = 0; j < HIDDEN / 32; j++)
        hs[wi][j * 32 + lane] = g_h[(size_t)i * HIDDEN + j * 32 + lane];
    __syncwarp();

    const int s = g_ssnd[i];
    const int r = g_srcv[i];

    const __half2* gp = (const __half2*)(g_gh + (size_t)s * HIDDEN * WIDTH) + lane;
    float2 acc = ((const float2*)(g_xb + (size_t)s * WIDTH))[lane];

    #pragma unroll 8
    for (int k = 0; k < HIDDEN; k++) {
        float hk = hs[wi][k];
        if (hk != 0.f) {
            float2 gv = __half22float2(gp[k * 32]);   // 128B coalesced row
            acc.x = fmaf(hk, gv.x, acc.x);
            acc.y = fmaf(hk, gv.y, acc.y);
        }
    }

    atomicAdd(out + (size_t)r * WIDTH + 2 * lane,     acc.x);
    atomicAdd(out + (size_t)r * WIDTH + 2 * lane + 1, acc.y);
}

// ---------------------------------------------------------------------------
// Launch: fork-join two streams. Side stream: prep_w2 -> gmat (the long pole).
// Default stream: sort chain + hidden + xb + out-zero (hidden under gmat).
// Streams/events created lazily on the first (non-capture) correctness call.
// ---------------------------------------------------------------------------
extern "C" void kernel_launch(void* const* d_in, const int* in_sizes, int n_in,
                              void* d_out, int out_size) {
    const float* x   = (const float*)d_in[0];
    const float* ea  = (const float*)d_in[1];
    const float* W1  = (const float*)d_in[2];
    const float* b1  = (const float*)d_in[3];
    const float* W2  = (const float*)d_in[4];
    const float* b2  = (const float*)d_in[5];
    const int*   snd = (const int*)d_in[6];
    const int*   rcv = (const int*)d_in[7];
    float* out = (float*)d_out;

    static cudaStream_t s2 = nullptr;
    static cudaEvent_t  evF = nullptr, evJ = nullptr;
    if (!s2) {
        cudaStreamCreateWithFlags(&s2, cudaStreamNonBlocking);
        cudaEventCreateWithFlags(&evF, cudaEventDisableTiming);
        cudaEventCreateWithFlags(&evJ, cudaEventDisableTiming);
        cudaFuncSetAttribute(k_gmat_hmma,
                             cudaFuncAttributeMaxDynamicSharedMemorySize, SM_TOT);
    }

    // ---- fork ----
    cudaEventRecord(evF, 0);
    cudaStreamWaitEvent(s2, evF, 0);

    // side stream: weight prep + the tensor GEMM (long pole)
    k_prep_w2<<<(HIDDEN * WIDTH * WIDTH + 255) / 256, 256, 0, s2>>>(W2);
    k_gmat_hmma<<<(NUM_NODES + 127) / 128, 256, SM_TOT, s2>>>(x);
    cudaEventRecord(evJ, s2);

    // default stream: everything else (independent of g)
    k_zero_cnt<<<(NUM_NODES + 255) / 256, 256>>>();
    k_count<<<(NUM_EDGES + 255) / 256, 256>>>(snd);
    k_scan<<<1, 1024>>>();
    k_fill<<<(NUM_EDGES + 255) / 256, 256>>>(snd, rcv);
    k_hidden<<<(NUM_EDGES * HIDDEN + 255) / 256, 256>>>(ea, W1, b1);
    k_xb<<<(NUM_NODES + 15) / 16, 256>>>(x, b2);
    k_zero<<<(NUM_NODES * WIDTH + 255) / 256, 256>>>(out, NUM_NODES * WIDTH);

    // ---- join, then the gather/scatter ----
    cudaStreamWaitEvent((cudaStream_t)0, evJ, 0);
    k_msg<<<NUM_EDGES / 8, 256>>>(out);
}

// round 13
// speedup vs baseline: 1.7823x; 1.0255x over previous
#include <cuda_runtime.h>
#include <cuda_bf16.h>
#include <cuda_fp16.h>
#include <cstdint>

// Problem constants (fixed by the dataset)
#define NUM_NODES 20000
#define NUM_EDGES 65536
#define WIDTH     64
#define EDGE_FEAT 6
#define HIDDEN    128

// Scratch (allocation-free rule: __device__ globals)
__device__ float  g_h [(size_t)NUM_EDGES * HIDDEN];                // 33.5 MB (SORTED edge order)
__device__ __half g_gh[(size_t)NUM_NODES * HIDDEN * WIDTH];        // 328 MB  g[n][k][v] fp16
__device__ float  g_xb[(size_t)NUM_NODES * WIDTH];                 // 5.1 MB
__device__ __nv_bfloat16 g_wt_hi[(size_t)HIDDEN * WIDTH * WIDTH];  // 2 MB  Wt[k][v][w] hi
__device__ __nv_bfloat16 g_wt_lo[(size_t)HIDDEN * WIDTH * WIDTH];  // 2 MB  Wt[k][v][w] lo
// edge sort-by-sender
__device__ int g_cnt [NUM_NODES];
__device__ int g_off [NUM_NODES + 1];
__device__ int g_inv [NUM_EDGES];     // original edge e -> sorted position
__device__ int g_ssnd[NUM_EDGES];     // sorted senders
__device__ int g_srcv[NUM_EDGES];     // sorted receivers

__device__ __forceinline__ void split_bf16(float a, unsigned short& hi, unsigned short& lo) {
    __nv_bfloat16 h = __float2bfloat16_rn(a);
    float r = a - __bfloat162float(h);
    __nv_bfloat16 l = __float2bfloat16_rn(r);
    hi = __bfloat16_as_ushort(h);
    lo = __bfloat16_as_ushort(l);
}

// Warp-level bf16 MMA (sm_80 PTX feature set — valid for plain sm_103 target)
#define MMA_BF16(c, a, b0, b1) \
    asm volatile("mma.sync.aligned.m16n8k16.row.col.f32.bf16.bf16.f32 " \
        "{%0,%1,%2,%3}, {%4,%5,%6,%7}, {%8,%9}, {%0,%1,%2,%3};" \
        : "+f"((c)[0]), "+f"((c)[1]), "+f"((c)[2]), "+f"((c)[3]) \
        : "r"((a)[0]), "r"((a)[1]), "r"((a)[2]), "r"((a)[3]), "r"(b0), "r"(b1))

// ---------------------------------------------------------------------------
// Zero kernels
// ---------------------------------------------------------------------------
__global__ void k_zero(float* __restrict__ out, int n) {
    int i = blockIdx.x * blockDim.x + threadIdx.x;
    if (i < n) out[i] = 0.f;
}
__global__ void k_zero_cnt() {
    int i = blockIdx.x * blockDim.x + threadIdx.x;
    if (i < NUM_NODES) g_cnt[i] = 0;
}

// ---------------------------------------------------------------------------
// Edge sort-by-sender: count -> scan (1 block) -> fill (inv/sorted arrays)
// ---------------------------------------------------------------------------
__global__ void k_count(const int* __restrict__ snd) {
    int i = blockIdx.x * blockDim.x + threadIdx.x;
    if (i < NUM_EDGES) atomicAdd(&g_cnt[snd[i]], 1);
}
__global__ __launch_bounds__(1024) void k_scan() {
    __shared__ int ps[1024];
    const int tid = threadIdx.x;
    const int CH  = (NUM_NODES + 1023) / 1024;   // 20
    const int base = tid * CH;
    int s = 0;
    #pragma unroll
    for (int j = 0; j < CH; j++) {
        int i = base + j;
        if (i < NUM_NODES) s += g_cnt[i];
    }
    ps[tid] = s;
    __syncthreads();
    for (int d = 1; d < 1024; d <<= 1) {         // Hillis-Steele inclusive scan
        int v = (tid >= d) ? ps[tid - d] : 0;
        __syncthreads();
        ps[tid] += v;
        __syncthreads();
    }
    int run = ps[tid] - s;                        // exclusive prefix of chunk
    #pragma unroll
    for (int j = 0; j < CH; j++) {
        int i = base + j;
        if (i < NUM_NODES) { g_off[i] = run; run += g_cnt[i]; g_cnt[i] = 0; }
    }
    if (tid == 1023) g_off[NUM_NODES] = run;
}
__global__ void k_fill(const int* __restrict__ snd, const int* __restrict__ rcv) {
    int i = blockIdx.x * blockDim.x + threadIdx.x;
    if (i >= NUM_EDGES) return;
    int s = snd[i];
    int pos = g_off[s] + atomicAdd(&g_cnt[s], 1);
    g_inv[i]     = pos;
    g_ssnd[pos]  = s;
    g_srcv[pos]  = rcv[i];
}

// ---------------------------------------------------------------------------
// h[pos][k] = relu( sum_f edge_attr[e][f]*W1[f][k] + b1[k] ), pos = g_inv[e]
// ---------------------------------------------------------------------------
__global__ void k_hidden(const float* __restrict__ ea,
                         const float* __restrict__ W1,
                         const float* __restrict__ b1) {
    int idx = blockIdx.x * blockDim.x + threadIdx.x;
    if (idx >= NUM_EDGES * HIDDEN) return;
    int e = idx >> 7;
    int j = idx & (HIDDEN - 1);
    const float* a = ea + (size_t)e * EDGE_FEAT;
    float s = __ldg(b1 + j);
    #pragma unroll
    for (int f = 0; f < EDGE_FEAT; f++)
        s = fmaf(__ldg(a + f), __ldg(W1 + f * HIDDEN + j), s);
    g_h[(size_t)g_inv[e] * HIDDEN + j] = fmaxf(s, 0.f);
}

// ---------------------------------------------------------------------------
// Wt[k][v][w] = W2[k][w*64+v], split bf16 hi/lo (col-major B for mma.row.col)
// ---------------------------------------------------------------------------
__global__ void k_prep_w2(const float* __restrict__ W2) {
    int idx = blockIdx.x * blockDim.x + threadIdx.x;
    if (idx >= HIDDEN * WIDTH * WIDTH) return;
    int k = idx >> 12, rem = idx & 4095, v = rem >> 6, w = rem & 63;
    float val = W2[(size_t)k * 4096 + w * 64 + v];
    unsigned short hi, lo;
    split_bf16(val, hi, lo);
    g_wt_hi[idx] = __ushort_as_bfloat16(hi);
    g_wt_lo[idx] = __ushort_as_bfloat16(lo);
}

// ---------------------------------------------------------------------------
// xb[n][v] = sum_w x[n][w]*b2[w*64+v].  16 nodes/block, 4 outputs/thread.
// ---------------------------------------------------------------------------
__global__ __launch_bounds__(256) void k_xb(const float* __restrict__ x,
                                            const float* __restrict__ b2) {
    __shared__ float b2s[WIDTH * WIDTH];       // 16 KB, [w][v]
    __shared__ float xs[16][WIDTH + 1];        // 16 node rows, padded
    const int t = threadIdx.x;
    for (int i = t; i < WIDTH * WIDTH; i += 256)
        b2s[i] = b2[i];
    {
        const int n0 = blockIdx.x * 16;
        for (int i = t; i < 16 * WIDTH; i += 256) {
            int nl = i >> 6, w = i & 63;
            int n = n0 + nl;
            xs[nl][w] = (n < NUM_NODES) ? x[(size_t)n * WIDTH + w] : 0.f;
        }
    }
    __syncthreads();

    const int nl = t >> 4;
    const int v4 = t & 15;
    float4 acc = make_float4(0.f, 0.f, 0.f, 0.f);
    #pragma unroll 8
    for (int w = 0; w < WIDTH; w++) {
        const float xv = xs[nl][w];
        const float4 b = *(const float4*)&b2s[w * WIDTH + v4 * 4];
        acc.x = fmaf(xv, b.x, acc.x);
        acc.y = fmaf(xv, b.y, acc.y);
        acc.z = fmaf(xv, b.z, acc.z);
        acc.w = fmaf(xv, b.w, acc.w);
    }
    const int n = blockIdx.x * 16 + nl;
    if (n < NUM_NODES)
        *(float4*)(g_xb + (size_t)n * WIDTH + v4 * 4) = acc;
}

// ---------------------------------------------------------------------------
// HMMA g-GEMM: g[n][k][v] = sum_w x[n][w]*Wt[k][v][w], stored as fp16.
// CTA = 128-node M-tile; 8 warps (4m x 2n), 32x32 C tile. Split-bf16.
// OCCUPANCY 2 (__launch_bounds__(256,2)): grid=157 at occ 1 meant 9 SMs ran
// two sequential CTAs (wave quantization -> 2x critical path). At occ 2 the
// whole grid is one wave + cross-CTA latency hiding. To fit the 124-reg cap,
// Al frags are re-loaded from smem per kt (Ah stays register-resident).
// B register-prefetched into double-buffered smem, ONE barrier/plane.
// ---------------------------------------------------------------------------
#define KP 72
#define SMA_HI 0
#define SMA_LO (128 * KP * 2)                  // 18432
#define SMB_BASE (2 * 128 * KP * 2)            // 36864
#define SMB(p, hl) (SMB_BASE + (p) * 18432 + (hl) * 9216)
#define SM_TOT (SMB_BASE + 2 * 18432)          // 73728 bytes (x2 CTAs = 147KB < 228KB)

__global__ __launch_bounds__(256, 2) void k_gmat_hmma(const float* __restrict__ x) {
    extern __shared__ char sm[];
    const int t    = threadIdx.x;
    const int lane = t & 31;
    const int warp = t >> 5;
    const int wm   = warp & 3;
    const int wn   = warp >> 2;
    const int n0   = blockIdx.x * 128;
    const int g    = lane >> 2;
    const int l4   = lane & 3;

    // ---- Stage A tile: x rows -> bf16 hi/lo, padded KP-stride rows ----
    {
        const int row  = t >> 1;
        const int half = t & 1;
        const int n    = n0 + row;
        float4 f4[8];
        if (n < NUM_NODES) {
            const float4* xr = (const float4*)(x + (size_t)n * WIDTH) + half * 8;
            #pragma unroll
            for (int j = 0; j < 8; j++) f4[j] = xr[j];
        } else {
            #pragma unroll
            for (int j = 0; j < 8; j++) f4[j] = make_float4(0.f, 0.f, 0.f, 0.f);
        }
        const float* f = (const float*)f4;
        #pragma unroll
        for (int c = 0; c < 4; c++) {
            uint32_t hw[4], lw[4];
            #pragma unroll
            for (int j = 0; j < 4; j++) {
                unsigned short h0, l0, h1, l1;
                split_bf16(f[c * 8 + j * 2 + 0], h0, l0);
                split_bf16(f[c * 8 + j * 2 + 1], h1, l1);
                hw[j] = (uint32_t)h0 | ((uint32_t)h1 << 16);
                lw[j] = (uint32_t)l0 | ((uint32_t)l1 << 16);
            }
            const uint32_t off = (uint32_t)row * (KP * 2) + half * 64 + c * 16;
            *(uint4*)(sm + SMA_HI + off) = make_uint4(hw[0], hw[1], hw[2], hw[3]);
            *(uint4*)(sm + SMA_LO + off) = make_uint4(lw[0], lw[1], lw[2], lw[3]);
        }
    }

    const uint4* wh4 = (const uint4*)g_wt_hi;
    const uint4* wl4 = (const uint4*)g_wt_lo;
    const int i0 = t, i1 = t + 256;
    const uint32_t so0 = (uint32_t)(i0 >> 3) * (KP * 2) + (i0 & 7) * 16;
    const uint32_t so1 = (uint32_t)(i1 >> 3) * (KP * 2) + (i1 & 7) * 16;

    // ---- Stage B plane 0 into buffer 0 ----
    {
        uint4 a0 = wh4[i0], a1 = wh4[i1], b0 = wl4[i0], b1 = wl4[i1];
        *(uint4*)(sm + SMB(0, 0) + so0) = a0;
        *(uint4*)(sm + SMB(0, 0) + so1) = a1;
        *(uint4*)(sm + SMB(0, 1) + so0) = b0;
        *(uint4*)(sm + SMB(0, 1) + so1) = b1;
    }
    __syncthreads();   // A tile + B plane 0 visible

    // ---- Load Ah fragments once (register-resident); Al re-read per plane ----
    uint32_t Ah[2][4][4];
    #pragma unroll
    for (int mt = 0; mt < 2; mt++) {
        #pragma unroll
        for (int kt = 0; kt < 4; kt++) {
            const int r0 = wm * 32 + mt * 16 + g;
            const int cb = kt * 16 + l4 * 2;
            Ah[mt][kt][0] = *(const uint32_t*)(sm + SMA_HI + ((size_t)r0 * KP + cb) * 2);
            Ah[mt][kt][1] = *(const uint32_t*)(sm + SMA_HI + ((size_t)(r0 + 8) * KP + cb) * 2);
            Ah[mt][kt][2] = *(const uint32_t*)(sm + SMA_HI + ((size_t)r0 * KP + cb + 8) * 2);
            Ah[mt][kt][3] = *(const uint32_t*)(sm + SMA_HI + ((size_t)(r0 + 8) * KP + cb + 8) * 2);
        }
    }

    // ---- Plane loop: compute from buf p; prefetch k+1 via regs -> buf p^1;
    //      ONE __syncthreads per plane (STS targets idle buffer). ----
    for (int k = 0; k < HIDDEN; k++) {
        const int p = k & 1;
        uint4 ph0, ph1, pl0, pl1;
        const bool pre = (k + 1 < HIDDEN);
        if (pre) {                        // issue LDGs early; MMAs hide latency
            const size_t base = (size_t)(k + 1) * 512;
            ph0 = wh4[base + i0];  ph1 = wh4[base + i1];
            pl0 = wl4[base + i0];  pl1 = wl4[base + i1];
        }

        float C[2][4][4];
        #pragma unroll
        for (int mt = 0; mt < 2; mt++)
            #pragma unroll
            for (int nt = 0; nt < 4; nt++)
                #pragma unroll
                for (int i = 0; i < 4; i++) C[mt][nt][i] = 0.f;

        #pragma unroll
        for (int kt = 0; kt < 4; kt++) {
            // Al frags for this kt from smem (conflict-free LDS; saves 32 regs)
            uint32_t Al[2][4];
            #pragma unroll
            for (int mt = 0; mt < 2; mt++) {
                const int r0 = wm * 32 + mt * 16 + g;
                const int cb = kt * 16 + l4 * 2;
                Al[mt][0] = *(const uint32_t*)(sm + SMA_LO + ((size_t)r0 * KP + cb) * 2);
                Al[mt][1] = *(const uint32_t*)(sm + SMA_LO + ((size_t)(r0 + 8) * KP + cb) * 2);
                Al[mt][2] = *(const uint32_t*)(sm + SMA_LO + ((size_t)r0 * KP + cb + 8) * 2);
                Al[mt][3] = *(const uint32_t*)(sm + SMA_LO + ((size_t)(r0 + 8) * KP + cb + 8) * 2);
            }
            #pragma unroll
            for (int nt = 0; nt < 4; nt++) {
                const uint32_t boff =
                    ((uint32_t)(wn * 32 + nt * 8 + g) * KP + kt * 16 + l4 * 2) * 2;
                const uint32_t bh0 = *(const uint32_t*)(sm + SMB(p, 0) + boff);
                const uint32_t bh1 = *(const uint32_t*)(sm + SMB(p, 0) + boff + 16);
                const uint32_t bl0 = *(const uint32_t*)(sm + SMB(p, 1) + boff);
                const uint32_t bl1 = *(const uint32_t*)(sm + SMB(p, 1) + boff + 16);
                #pragma unroll
                for (int mt = 0; mt < 2; mt++) {
                    MMA_BF16(C[mt][nt], Ah[mt][kt], bh0, bh1);
                    MMA_BF16(C[mt][nt], Ah[mt][kt], bl0, bl1);
                    MMA_BF16(C[mt][nt], Al[mt], bh0, bh1);
                }
            }
        }

        if (pre) {                        // STS into the idle buffer (no race)
            *(uint4*)(sm + SMB(p ^ 1, 0) + so0) = ph0;
            *(uint4*)(sm + SMB(p ^ 1, 0) + so1) = ph1;
            *(uint4*)(sm + SMB(p ^ 1, 1) + so0) = pl0;
            *(uint4*)(sm + SMB(p ^ 1, 1) + so1) = pl1;
        }

        // Store this k-plane as fp16 (halves g DRAM traffic on both sides)
        #pragma unroll
        for (int mt = 0; mt < 2; mt++) {
            const int n1 = n0 + wm * 32 + mt * 16 + g;
            const int n2 = n1 + 8;
            #pragma unroll
            for (int nt = 0; nt < 4; nt++) {
                const int col = wn * 32 + nt * 8 + l4 * 2;
                if (n1 < NUM_NODES)
                    *(__half2*)(g_gh + ((size_t)n1 * HIDDEN + k) * WIDTH + col) =
                        __floats2half2_rn(C[mt][nt][0], C[mt][nt][1]);
                if (n2 < NUM_NODES)
                    *(__half2*)(g_gh + ((size_t)n2 * HIDDEN + k) * WIDTH + col) =
                        __floats2half2_rn(C[mt][nt][2], C[mt][nt][3]);
            }
        }

        if (pre) __syncthreads();         // buf p^1 ready; buf p free next plane
    }
}

// ---------------------------------------------------------------------------
// Per sorted edge i: msg[v] = sum_k h[i][k]*g[s][k][v] + xb[s][v];
// g rows are fp16 (one 128B line per k). atomicAdd into out[r][v].
// Warp per edge; relu-sparsity + sender locality (sorted).
// ---------------------------------------------------------------------------
__global__ __launch_bounds__(256) void k_msg(float* __restrict__ out) {
    __shared__ float hs[8][HIDDEN];
    const int wi   = threadIdx.x >> 5;
    const int lane = threadIdx.x & 31;
    const int i    = blockIdx.x * 8 + wi;
    if (i >= NUM_EDGES) return;

    #pragma unroll
    for (int j = 0; j < HIDDEN / 32; j++)
        hs[wi][j * 32 + lane] = g_h[(size_t)i * HIDDEN + j * 32 + lane];
    __syncwarp();

    const int s = g_ssnd[i];
    const int r = g_srcv[i];

    const __half2* gp = (const __half2*)(g_gh + (size_t)s * HIDDEN * WIDTH) + lane;
    float2 acc = ((const float2*)(g_xb + (size_t)s * WIDTH))[lane];

    #pragma unroll 8
    for (int k = 0; k < HIDDEN; k++) {
        float hk = hs[wi][k];
        if (hk != 0.f) {
            float2 gv = __half22float2(gp[k * 32]);   // 128B coalesced row
            acc.x = fmaf(hk, gv.x, acc.x);
            acc.y = fmaf(hk, gv.y, acc.y);
        }
    }

    atomicAdd(out + (size_t)r * WIDTH + 2 * lane,     acc.x);
    atomicAdd(out + (size_t)r * WIDTH + 2 * lane + 1, acc.y);
}

// ---------------------------------------------------------------------------
// Launch: fork-join two streams. Side stream: prep_w2 -> gmat (the long pole).
// Default stream: sort chain + hidden + xb + out-zero (hidden under gmat).
// Streams/events created lazily on the first (non-capture) correctness call.
// ---------------------------------------------------------------------------
extern "C" void kernel_launch(void* const* d_in, const int* in_sizes, int n_in,
                              void* d_out, int out_size) {
    const float* x   = (const float*)d_in[0];
    const float* ea  = (const float*)d_in[1];
    const float* W1  = (const float*)d_in[2];
    const float* b1  = (const float*)d_in[3];
    const float* W2  = (const float*)d_in[4];
    const float* b2  = (const float*)d_in[5];
    const int*   snd = (const int*)d_in[6];
    const int*   rcv = (const int*)d_in[7];
    float* out = (float*)d_out;

    static cudaStream_t s2 = nullptr;
    static cudaEvent_t  evF = nullptr, evJ = nullptr;
    if (!s2) {
        cudaStreamCreateWithFlags(&s2, cudaStreamNonBlocking);
        cudaEventCreateWithFlags(&evF, cudaEventDisableTiming);
        cudaEventCreateWithFlags(&evJ, cudaEventDisableTiming);
        cudaFuncSetAttribute(k_gmat_hmma,
                             cudaFuncAttributeMaxDynamicSharedMemorySize, SM_TOT);
    }

    // ---- fork ----
    cudaEventRecord(evF, 0);
    cudaStreamWaitEvent(s2, evF, 0);

    // side stream: weight prep + the tensor GEMM (long pole)
    k_prep_w2<<<(HIDDEN * WIDTH * WIDTH + 255) / 256, 256, 0, s2>>>(W2);
    k_gmat_hmma<<<(NUM_NODES + 127) / 128, 256, SM_TOT, s2>>>(x);
    cudaEventRecord(evJ, s2);

    // default stream: everything else (independent of g)
    k_zero_cnt<<<(NUM_NODES + 255) / 256, 256>>>();
    k_count<<<(NUM_EDGES + 255) / 256, 256>>>(snd);
    k_scan<<<1, 1024>>>();
    k_fill<<<(NUM_EDGES + 255) / 256, 256>>>(snd, rcv);
    k_hidden<<<(NUM_EDGES * HIDDEN + 255) / 256, 256>>>(ea, W1, b1);
    k_xb<<<(NUM_NODES + 15) / 16, 256>>>(x, b2);
    k_zero<<<(NUM_NODES * WIDTH + 255) / 256, 256>>>(out, NUM_NODES * WIDTH);

    // ---- join, then the gather/scatter ----
    cudaStreamWaitEvent((cudaStream_t)0, evJ, 0);
    k_msg<<<NUM_EDGES / 8, 256>>>(out);
}

// round 14
// speedup vs baseline: 2.4956x; 1.4002x over previous
#include <cuda_runtime.h>
#include <cuda_fp16.h>
#include <cstdint>

// Problem constants (fixed by the dataset)
#define NUM_NODES 20000
#define NUM_EDGES 65536
#define WIDTH     64
#define EDGE_FEAT 6
#define HIDDEN    128

// Scratch (allocation-free rule: __device__ globals)
__device__ float  g_h [(size_t)NUM_EDGES * HIDDEN];                // 33.5 MB (SORTED edge order)
__device__ __half g_gh[(size_t)NUM_NODES * HIDDEN * WIDTH];        // 328 MB  g[n][k][v] fp16
__device__ float  g_xb[(size_t)NUM_NODES * WIDTH];                 // 5.1 MB
__device__ __half g_wt[(size_t)HIDDEN * WIDTH * WIDTH];            // 2 MB  Wt[k][v][w] fp16
// edge sort-by-sender
__device__ int g_cnt [NUM_NODES];
__device__ int g_off [NUM_NODES + 1];
__device__ int g_inv [NUM_EDGES];     // original edge e -> sorted position
__device__ int g_ssnd[NUM_EDGES];     // sorted senders
__device__ int g_srcv[NUM_EDGES];     // sorted receivers

// Warp-level fp16 MMA (sm_80 PTX feature set — valid for plain sm_103 target)
#define MMA_FP16(c, a, b0, b1) \
    asm volatile("mma.sync.aligned.m16n8k16.row.col.f32.f16.f16.f32 " \
        "{%0,%1,%2,%3}, {%4,%5,%6,%7}, {%8,%9}, {%0,%1,%2,%3};" \
        : "+f"((c)[0]), "+f"((c)[1]), "+f"((c)[2]), "+f"((c)[3]) \
        : "r"((a)[0]), "r"((a)[1]), "r"((a)[2]), "r"((a)[3]), "r"(b0), "r"(b1))

// ---------------------------------------------------------------------------
// Zero kernels
// ---------------------------------------------------------------------------
__global__ void k_zero(float* __restrict__ out, int n) {
    int i = blockIdx.x * blockDim.x + threadIdx.x;
    if (i < n) out[i] = 0.f;
}
__global__ void k_zero_cnt() {
    int i = blockIdx.x * blockDim.x + threadIdx.x;
    if (i < NUM_NODES) g_cnt[i] = 0;
}

// ---------------------------------------------------------------------------
// Edge sort-by-sender: count -> scan (1 block) -> fill (inv/sorted arrays)
// ---------------------------------------------------------------------------
__global__ void k_count(const int* __restrict__ snd) {
    int i = blockIdx.x * blockDim.x + threadIdx.x;
    if (i < NUM_EDGES) atomicAdd(&g_cnt[snd[i]], 1);
}
__global__ __launch_bounds__(1024) void k_scan() {
    __shared__ int ps[1024];
    const int tid = threadIdx.x;
    const int CH  = (NUM_NODES + 1023) / 1024;   // 20
    const int base = tid * CH;
    int s = 0;
    #pragma unroll
    for (int j = 0; j < CH; j++) {
        int i = base + j;
        if (i < NUM_NODES) s += g_cnt[i];
    }
    ps[tid] = s;
    __syncthreads();
    for (int d = 1; d < 1024; d <<= 1) {         // Hillis-Steele inclusive scan
        int v = (tid >= d) ? ps[tid - d] : 0;
        __syncthreads();
        ps[tid] += v;
        __syncthreads();
    }
    int run = ps[tid] - s;                        // exclusive prefix of chunk
    #pragma unroll
    for (int j = 0; j < CH; j++) {
        int i = base + j;
        if (i < NUM_NODES) { g_off[i] = run; run += g_cnt[i]; g_cnt[i] = 0; }
    }
    if (tid == 1023) g_off[NUM_NODES] = run;
}
__global__ void k_fill(const int* __restrict__ snd, const int* __restrict__ rcv) {
    int i = blockIdx.x * blockDim.x + threadIdx.x;
    if (i >= NUM_EDGES) return;
    int s = snd[i];
    int pos = g_off[s] + atomicAdd(&g_cnt[s], 1);
    g_inv[i]     = pos;
    g_ssnd[pos]  = s;
    g_srcv[pos]  = rcv[i];
}

// ---------------------------------------------------------------------------
// h[pos][k] = relu( sum_f edge_attr[e][f]*W1[f][k] + b1[k] ), pos = g_inv[e]
// ---------------------------------------------------------------------------
__global__ void k_hidden(const float* __restrict__ ea,
                         const float* __restrict__ W1,
                         const float* __restrict__ b1) {
    int idx = blockIdx.x * blockDim.x + threadIdx.x;
    if (idx >= NUM_EDGES * HIDDEN) return;
    int e = idx >> 7;
    int j = idx & (HIDDEN - 1);
    const float* a = ea + (size_t)e * EDGE_FEAT;
    float s = __ldg(b1 + j);
    #pragma unroll
    for (int f = 0; f < EDGE_FEAT; f++)
        s = fmaf(__ldg(a + f), __ldg(W1 + f * HIDDEN + j), s);
    g_h[(size_t)g_inv[e] * HIDDEN + j] = fmaxf(s, 0.f);
}

// ---------------------------------------------------------------------------
// Wt[k][v][w] = W2[k][w*64+v] as fp16 (col-major B for mma.row.col)
// ---------------------------------------------------------------------------
__global__ void k_prep_w2(const float* __restrict__ W2) {
    int idx = blockIdx.x * blockDim.x + threadIdx.x;
    if (idx >= HIDDEN * WIDTH * WIDTH) return;
    int k = idx >> 12, rem = idx & 4095, v = rem >> 6, w = rem & 63;
    g_wt[idx] = __float2half_rn(W2[(size_t)k * 4096 + w * 64 + v]);
}

// ---------------------------------------------------------------------------
// xb[n][v] = sum_w x[n][w]*b2[w*64+v].  16 nodes/block, 4 outputs/thread.
// ---------------------------------------------------------------------------
__global__ __launch_bounds__(256) void k_xb(const float* __restrict__ x,
                                            const float* __restrict__ b2) {
    __shared__ float b2s[WIDTH * WIDTH];       // 16 KB, [w][v]
    __shared__ float xs[16][WIDTH + 1];        // 16 node rows, padded
    const int t = threadIdx.x;
    for (int i = t; i < WIDTH * WIDTH; i += 256)
        b2s[i] = b2[i];
    {
        const int n0 = blockIdx.x * 16;
        for (int i = t; i < 16 * WIDTH; i += 256) {
            int nl = i >> 6, w = i & 63;
            int n = n0 + nl;
            xs[nl][w] = (n < NUM_NODES) ? x[(size_t)n * WIDTH + w] : 0.f;
        }
    }
    __syncthreads();

    const int nl = t >> 4;
    const int v4 = t & 15;
    float4 acc = make_float4(0.f, 0.f, 0.f, 0.f);
    #pragma unroll 8
    for (int w = 0; w < WIDTH; w++) {
        const float xv = xs[nl][w];
        const float4 b = *(const float4*)&b2s[w * WIDTH + v4 * 4];
        acc.x = fmaf(xv, b.x, acc.x);
        acc.y = fmaf(xv, b.y, acc.y);
        acc.z = fmaf(xv, b.z, acc.z);
        acc.w = fmaf(xv, b.w, acc.w);
    }
    const int n = blockIdx.x * 16 + nl;
    if (n < NUM_NODES)
        *(float4*)(g_xb + (size_t)n * WIDTH + v4 * 4) = acc;
}

// ---------------------------------------------------------------------------
// HMMA g-GEMM: g[n][k][v] = sum_w x[n][w]*Wt[k][v][w], fp16 in / fp32 acc /
// fp16 out. SINGLE MMA group (no precision split): fp16 operand error
// ~2.4e-4/element rides inside the 1e-3 budget -> 3x less tensor work, 3x
// less operand LDS vs split-bf16. CTA = 128-node M-tile; 8 warps (4m x 2n),
// 32x32 C tile. A frags register-resident; B register-prefetched into
// double-buffered smem, ONE barrier/plane. occ 2.
// ---------------------------------------------------------------------------
#define KP 72
#define SMA 0                                  // 128 rows * 144B = 18432
#define SMB_BASE (128 * KP * 2)                // 18432
#define SMB(p) (SMB_BASE + (p) * 9216)         // 64 rows * 144B each
#define SM_TOT (SMB_BASE + 2 * 9216)           // 36864 bytes (x2 CTAs = 74KB)

__global__ __launch_bounds__(256, 2) void k_gmat_hmma(const float* __restrict__ x) {
    extern __shared__ char sm[];
    const int t    = threadIdx.x;
    const int lane = t & 31;
    const int warp = t >> 5;
    const int wm   = warp & 3;
    const int wn   = warp >> 2;
    const int n0   = blockIdx.x * 128;
    const int g    = lane >> 2;
    const int l4   = lane & 3;

    // ---- Stage A tile: x rows -> fp16, padded KP-stride rows ----
    {
        const int row  = t >> 1;
        const int half = t & 1;
        const int n    = n0 + row;
        float4 f4[8];
        if (n < NUM_NODES) {
            const float4* xr = (const float4*)(x + (size_t)n * WIDTH) + half * 8;
            #pragma unroll
            for (int j = 0; j < 8; j++) f4[j] = xr[j];
        } else {
            #pragma unroll
            for (int j = 0; j < 8; j++) f4[j] = make_float4(0.f, 0.f, 0.f, 0.f);
        }
        const float* f = (const float*)f4;
        #pragma unroll
        for (int c = 0; c < 4; c++) {
            uint32_t hw[4];
            #pragma unroll
            for (int j = 0; j < 4; j++) {
                __half2 h2 = __floats2half2_rn(f[c * 8 + j * 2], f[c * 8 + j * 2 + 1]);
                hw[j] = *(uint32_t*)&h2;
            }
            const uint32_t off = (uint32_t)row * (KP * 2) + half * 64 + c * 16;
            *(uint4*)(sm + SMA + off) = make_uint4(hw[0], hw[1], hw[2], hw[3]);
        }
    }

    const uint4* wt4 = (const uint4*)g_wt;     // 512 uint4 per plane
    const int i0 = t, i1 = t + 256;
    const uint32_t so0 = (uint32_t)(i0 >> 3) * (KP * 2) + (i0 & 7) * 16;
    const uint32_t so1 = (uint32_t)(i1 >> 3) * (KP * 2) + (i1 & 7) * 16;

    // ---- Stage B plane 0 into buffer 0 ----
    {
        uint4 a0 = wt4[i0], a1 = wt4[i1];
        *(uint4*)(sm + SMB(0) + so0) = a0;
        *(uint4*)(sm + SMB(0) + so1) = a1;
    }
    __syncthreads();   // A tile + B plane 0 visible

    // ---- Load A fragments once (register-resident, 32 regs) ----
    uint32_t Ah[2][4][4];
    #pragma unroll
    for (int mt = 0; mt < 2; mt++) {
        #pragma unroll
        for (int kt = 0; kt < 4; kt++) {
            const int r0 = wm * 32 + mt * 16 + g;
            const int cb = kt * 16 + l4 * 2;
            Ah[mt][kt][0] = *(const uint32_t*)(sm + SMA + ((size_t)r0 * KP + cb) * 2);
            Ah[mt][kt][1] = *(const uint32_t*)(sm + SMA + ((size_t)(r0 + 8) * KP + cb) * 2);
            Ah[mt][kt][2] = *(const uint32_t*)(sm + SMA + ((size_t)r0 * KP + cb + 8) * 2);
            Ah[mt][kt][3] = *(const uint32_t*)(sm + SMA + ((size_t)(r0 + 8) * KP + cb + 8) * 2);
        }
    }

    // ---- Plane loop: compute from buf p; prefetch k+1 via regs -> buf p^1;
    //      ONE __syncthreads per plane. 32 MMAs/warp/plane. ----
    for (int k = 0; k < HIDDEN; k++) {
        const int p = k & 1;
        uint4 ph0, ph1;
        const bool pre = (k + 1 < HIDDEN);
        if (pre) {                        // issue LDGs early; MMAs hide latency
            const size_t base = (size_t)(k + 1) * 512;
            ph0 = wt4[base + i0];  ph1 = wt4[base + i1];
        }

        float C[2][4][4];
        #pragma unroll
        for (int mt = 0; mt < 2; mt++)
            #pragma unroll
            for (int nt = 0; nt < 4; nt++)
                #pragma unroll
                for (int i = 0; i < 4; i++) C[mt][nt][i] = 0.f;

        #pragma unroll
        for (int kt = 0; kt < 4; kt++) {
            #pragma unroll
            for (int nt = 0; nt < 4; nt++) {
                const uint32_t boff =
                    ((uint32_t)(wn * 32 + nt * 8 + g) * KP + kt * 16 + l4 * 2) * 2;
                const uint32_t b0 = *(const uint32_t*)(sm + SMB(p) + boff);
                const uint32_t b1 = *(const uint32_t*)(sm + SMB(p) + boff + 16);
                #pragma unroll
                for (int mt = 0; mt < 2; mt++)
                    MMA_FP16(C[mt][nt], Ah[mt][kt], b0, b1);
            }
        }

        if (pre) {                        // STS into the idle buffer (no race)
            *(uint4*)(sm + SMB(p ^ 1) + so0) = ph0;
            *(uint4*)(sm + SMB(p ^ 1) + so1) = ph1;
        }

        // Store this k-plane as fp16
        #pragma unroll
        for (int mt = 0; mt < 2; mt++) {
            const int n1 = n0 + wm * 32 + mt * 16 + g;
            const int n2 = n1 + 8;
            #pragma unroll
            for (int nt = 0; nt < 4; nt++) {
                const int col = wn * 32 + nt * 8 + l4 * 2;
                if (n1 < NUM_NODES)
                    *(__half2*)(g_gh + ((size_t)n1 * HIDDEN + k) * WIDTH + col) =
                        __floats2half2_rn(C[mt][nt][0], C[mt][nt][1]);
                if (n2 < NUM_NODES)
                    *(__half2*)(g_gh + ((size_t)n2 * HIDDEN + k) * WIDTH + col) =
                        __floats2half2_rn(C[mt][nt][2], C[mt][nt][3]);
            }
        }

        if (pre) __syncthreads();         // buf p^1 ready; buf p free next plane
    }
}

// ---------------------------------------------------------------------------
// Per sorted edge i: msg[v] = sum_k h[i][k]*g[s][k][v] + xb[s][v];
// g rows are fp16 (one 128B line per k). atomicAdd into out[r][v].
// Warp per edge; relu-sparsity + sender locality (sorted).
// ---------------------------------------------------------------------------
__global__ __launch_bounds__(256) void k_msg(float* __restrict__ out) {
    __shared__ float hs[8][HIDDEN];
    const int wi   = threadIdx.x >> 5;
    const int lane = threadIdx.x & 31;
    const int i    = blockIdx.x * 8 + wi;
    if (i >= NUM_EDGES) return;

    #pragma unroll
    for (int j = 0; j < HIDDEN / 32; j++)
        hs[wi][j * 32 + lane] = g_h[(size_t)i * HIDDEN + j * 32 + lane];
    __syncwarp();

    const int s = g_ssnd[i];
    const int r = g_srcv[i];

    const __half2* gp = (const __half2*)(g_gh + (size_t)s * HIDDEN * WIDTH) + lane;
    float2 acc = ((const float2*)(g_xb + (size_t)s * WIDTH))[lane];

    #pragma unroll 8
    for (int k = 0; k < HIDDEN; k++) {
        float hk = hs[wi][k];
        if (hk != 0.f) {
            float2 gv = __half22float2(gp[k * 32]);   // 128B coalesced row
            acc.x = fmaf(hk, gv.x, acc.x);
            acc.y = fmaf(hk, gv.y, acc.y);
        }
    }

    atomicAdd(out + (size_t)r * WIDTH + 2 * lane,     acc.x);
    atomicAdd(out + (size_t)r * WIDTH + 2 * lane + 1, acc.y);
}

// ---------------------------------------------------------------------------
// Launch: fork-join two streams (overlap identical to R13). Submission order
// rearranged so k_gmat_hmma is the 6th launch -> ncu (-s 5 -c 1) finally
// profiles the long pole instead of a 4us helper.
// ---------------------------------------------------------------------------
extern "C" void kernel_launch(void* const* d_in, const int* in_sizes, int n_in,
                              void* d_out, int out_size) {
    const float* x   = (const float*)d_in[0];
    const float* ea  = (const float*)d_in[1];
    const float* W1  = (const float*)d_in[2];
    const float* b1  = (const float*)d_in[3];
    const float* W2  = (const float*)d_in[4];
    const float* b2  = (const float*)d_in[5];
    const int*   snd = (const int*)d_in[6];
    const int*   rcv = (const int*)d_in[7];
    float* out = (float*)d_out;

    static cudaStream_t s2 = nullptr;
    static cudaEvent_t  evF = nullptr, evJ = nullptr;
    if (!s2) {
        cudaStreamCreateWithFlags(&s2, cudaStreamNonBlocking);
        cudaEventCreateWithFlags(&evF, cudaEventDisableTiming);
        cudaEventCreateWithFlags(&evJ, cudaEventDisableTiming);
        cudaFuncSetAttribute(k_gmat_hmma,
                             cudaFuncAttributeMaxDynamicSharedMemorySize, SM_TOT);
    }

    // ---- fork ----
    cudaEventRecord(evF, 0);
    cudaStreamWaitEvent(s2, evF, 0);

    // default stream first (launches 1-4)
    k_zero_cnt<<<(NUM_NODES + 255) / 256, 256>>>();
    k_count<<<(NUM_EDGES + 255) / 256, 256>>>(snd);
    k_scan<<<1, 1024>>>();
    k_fill<<<(NUM_EDGES + 255) / 256, 256>>>(snd, rcv);

    // side stream (launches 5-6; executes concurrently from evF)
    k_prep_w2<<<(HIDDEN * WIDTH * WIDTH + 255) / 256, 256, 0, s2>>>(W2);
    k_gmat_hmma<<<(NUM_NODES + 127) / 128, 256, SM_TOT, s2>>>(x);   // 6th: profiled
    cudaEventRecord(evJ, s2);

    // rest of default stream (independent of g)
    k_hidden<<<(NUM_EDGES * HIDDEN + 255) / 256, 256>>>(ea, W1, b1);
    k_xb<<<(NUM_NODES + 15) / 16, 256>>>(x, b2);
    k_zero<<<(NUM_NODES * WIDTH + 255) / 256, 256>>>(out, NUM_NODES * WIDTH);

    // ---- join, then the gather/scatter ----
    cudaStreamWaitEvent((cudaStream_t)0, evJ, 0);
    k_msg<<<NUM_EDGES / 8, 256>>>(out);
}